// round 1
// baseline (speedup 1.0000x reference)
#include <cuda_runtime.h>
#include <cstdint>

#define CC 19
#define NP 361
#define DD 256
#define BB 32
#define HH 8
#define HDIM 32
#define MX (BB*NP)   // 11552
#define MQ (BB*CC)   // 608

// ---------------- scratch (device globals: no allocations allowed) ----------
__device__ float g_K[(size_t)CC*BB*NP*DD];   // [c][b][pos][e]
__device__ float g_V[(size_t)CC*BB*NP*DD];
__device__ float g_Q[(size_t)CC*BB*CC*DD];   // [c][b][j][e]
__device__ float g_AO[(size_t)CC*BB*CC*DD];
__device__ float g_Mc[(size_t)CC*DD*DD];     // combined w_fuse @ w_out[c]
__device__ float g_bc[(size_t)CC*DD];        // combined bias

// ---------------- K/V projection GEMM ---------------------------------------
// grid (91, 4, 19): per channel, X(11552x256) @ Wkv^T(512x256)
__global__ __launch_bounds__(256, 2)
void gemm_kv(const float* __restrict__ x, const float* __restrict__ w_in,
             const float* __restrict__ b_in) {
    const int c  = blockIdx.z;
    const int m0 = blockIdx.x * 128;
    const int n0 = blockIdx.y * 128;           // within [0,512)
    __shared__ float As[8][128];
    __shared__ float Bs[8][128];
    const int tid   = threadIdx.x;
    const int ldRow = tid >> 1;
    const int ldCol = (tid & 1) << 2;

    int am = m0 + ldRow; if (am > MX - 1) am = MX - 1;
    const float* Ap = x + (size_t)am * DD + ldCol;
    const float* Bp = w_in + ((size_t)c * 768 + 256 + n0 + ldRow) * DD + ldCol;

    const int ty = tid >> 4, tx = tid & 15;
    float acc[8][8];
    #pragma unroll
    for (int i = 0; i < 8; i++)
        #pragma unroll
        for (int j = 0; j < 8; j++) acc[i][j] = 0.f;

    for (int kt = 0; kt < DD; kt += 8) {
        float4 a = *(const float4*)(Ap + kt);
        float4 b = *(const float4*)(Bp + kt);
        As[ldCol+0][ldRow]=a.x; As[ldCol+1][ldRow]=a.y;
        As[ldCol+2][ldRow]=a.z; As[ldCol+3][ldRow]=a.w;
        Bs[ldCol+0][ldRow]=b.x; Bs[ldCol+1][ldRow]=b.y;
        Bs[ldCol+2][ldRow]=b.z; Bs[ldCol+3][ldRow]=b.w;
        __syncthreads();
        #pragma unroll
        for (int k = 0; k < 8; k++) {
            float ra[8], rb[8];
            *(float4*)&ra[0] = *(const float4*)&As[k][ty*8];
            *(float4*)&ra[4] = *(const float4*)&As[k][ty*8+4];
            *(float4*)&rb[0] = *(const float4*)&Bs[k][tx*8];
            *(float4*)&rb[4] = *(const float4*)&Bs[k][tx*8+4];
            #pragma unroll
            for (int i = 0; i < 8; i++)
                #pragma unroll
                for (int j = 0; j < 8; j++)
                    acc[i][j] = fmaf(ra[i], rb[j], acc[i][j]);
        }
        __syncthreads();
    }

    const float* bi = b_in + c*768 + 256 + n0 + tx*8;
    float bv[8];
    #pragma unroll
    for (int j = 0; j < 8; j++) bv[j] = bi[j];

    #pragma unroll
    for (int i = 0; i < 8; i++) {
        int m = m0 + ty*8 + i;
        if (m >= MX) break;
        int bb = m / NP, pos = m % NP;
        float* base = (n0 < 256) ? g_K : g_V;
        int e0 = ((n0 < 256) ? n0 : n0 - 256) + tx*8;
        float* op = base + (((size_t)c*BB + bb)*NP + pos)*DD + e0;
        #pragma unroll
        for (int j = 0; j < 8; j += 4) {
            float4 v;
            v.x = acc[i][j+0] + bv[j+0];
            v.y = acc[i][j+1] + bv[j+1];
            v.z = acc[i][j+2] + bv[j+2];
            v.w = acc[i][j+3] + bv[j+3];
            *(float4*)(op + j) = v;
        }
    }
}

// ---------------- Q projection GEMM ------------------------------------------
// grid (5, 2, 19): per channel, rows m=b*19+j gather x[b*361 + c*19 + j]
__global__ __launch_bounds__(256, 2)
void gemm_q(const float* __restrict__ x, const float* __restrict__ w_in,
            const float* __restrict__ b_in) {
    const int c  = blockIdx.z;
    const int m0 = blockIdx.x * 128;
    const int n0 = blockIdx.y * 128;
    __shared__ float As[8][128];
    __shared__ float Bs[8][128];
    const int tid   = threadIdx.x;
    const int ldRow = tid >> 1;
    const int ldCol = (tid & 1) << 2;

    int am = m0 + ldRow; if (am > MQ - 1) am = MQ - 1;
    int xrow = (am / CC) * NP + c * CC + (am % CC);
    const float* Ap = x + (size_t)xrow * DD + ldCol;
    const float* Bp = w_in + ((size_t)c * 768 + n0 + ldRow) * DD + ldCol;

    const int ty = tid >> 4, tx = tid & 15;
    float acc[8][8];
    #pragma unroll
    for (int i = 0; i < 8; i++)
        #pragma unroll
        for (int j = 0; j < 8; j++) acc[i][j] = 0.f;

    for (int kt = 0; kt < DD; kt += 8) {
        float4 a = *(const float4*)(Ap + kt);
        float4 b = *(const float4*)(Bp + kt);
        As[ldCol+0][ldRow]=a.x; As[ldCol+1][ldRow]=a.y;
        As[ldCol+2][ldRow]=a.z; As[ldCol+3][ldRow]=a.w;
        Bs[ldCol+0][ldRow]=b.x; Bs[ldCol+1][ldRow]=b.y;
        Bs[ldCol+2][ldRow]=b.z; Bs[ldCol+3][ldRow]=b.w;
        __syncthreads();
        #pragma unroll
        for (int k = 0; k < 8; k++) {
            float ra[8], rb[8];
            *(float4*)&ra[0] = *(const float4*)&As[k][ty*8];
            *(float4*)&ra[4] = *(const float4*)&As[k][ty*8+4];
            *(float4*)&rb[0] = *(const float4*)&Bs[k][tx*8];
            *(float4*)&rb[4] = *(const float4*)&Bs[k][tx*8+4];
            #pragma unroll
            for (int i = 0; i < 8; i++)
                #pragma unroll
                for (int j = 0; j < 8; j++)
                    acc[i][j] = fmaf(ra[i], rb[j], acc[i][j]);
        }
        __syncthreads();
    }

    const float* bi = b_in + c*768 + n0 + tx*8;
    float bv[8];
    #pragma unroll
    for (int j = 0; j < 8; j++) bv[j] = bi[j];

    #pragma unroll
    for (int i = 0; i < 8; i++) {
        int m = m0 + ty*8 + i;
        if (m >= MQ) break;
        float* op = g_Q + ((size_t)c*MQ + m)*DD + n0 + tx*8;
        #pragma unroll
        for (int j = 0; j < 8; j += 4) {
            float4 v;
            v.x = acc[i][j+0] + bv[j+0];
            v.y = acc[i][j+1] + bv[j+1];
            v.z = acc[i][j+2] + bv[j+2];
            v.w = acc[i][j+3] + bv[j+3];
            *(float4*)(op + j) = v;
        }
    }
}

// ---------------- combined weight: Mc[c] = w_fuse @ w_out[c] -----------------
// grid (2, 2, 19); B operand (w_out[c]) is k-row-major => non-transposed load
__global__ __launch_bounds__(256, 2)
void gemm_comb(const float* __restrict__ w_fuse, const float* __restrict__ w_out) {
    const int c  = blockIdx.z;
    const int m0 = blockIdx.x * 128;
    const int n0 = blockIdx.y * 128;
    __shared__ float As[8][128];
    __shared__ float Bs[8][128];
    const int tid  = threadIdx.x;
    const int aRow = tid >> 1, aCol = (tid & 1) << 2;
    const int bK   = tid >> 5, bN = (tid & 31) << 2;

    const float* Ap = w_fuse + (size_t)(m0 + aRow) * DD + aCol;
    const float* Bbase = w_out + (size_t)c * DD * DD;

    const int ty = tid >> 4, tx = tid & 15;
    float acc[8][8];
    #pragma unroll
    for (int i = 0; i < 8; i++)
        #pragma unroll
        for (int j = 0; j < 8; j++) acc[i][j] = 0.f;

    for (int kt = 0; kt < DD; kt += 8) {
        float4 a = *(const float4*)(Ap + kt);
        float4 b = *(const float4*)(Bbase + (size_t)(kt + bK) * DD + n0 + bN);
        As[aCol+0][aRow]=a.x; As[aCol+1][aRow]=a.y;
        As[aCol+2][aRow]=a.z; As[aCol+3][aRow]=a.w;
        *(float4*)&Bs[bK][bN] = b;
        __syncthreads();
        #pragma unroll
        for (int k = 0; k < 8; k++) {
            float ra[8], rb[8];
            *(float4*)&ra[0] = *(const float4*)&As[k][ty*8];
            *(float4*)&ra[4] = *(const float4*)&As[k][ty*8+4];
            *(float4*)&rb[0] = *(const float4*)&Bs[k][tx*8];
            *(float4*)&rb[4] = *(const float4*)&Bs[k][tx*8+4];
            #pragma unroll
            for (int i = 0; i < 8; i++)
                #pragma unroll
                for (int j = 0; j < 8; j++)
                    acc[i][j] = fmaf(ra[i], rb[j], acc[i][j]);
        }
        __syncthreads();
    }

    #pragma unroll
    for (int i = 0; i < 8; i++) {
        int m = m0 + ty*8 + i;
        float* op = g_Mc + ((size_t)c*DD + m)*DD + n0 + tx*8;
        #pragma unroll
        for (int j = 0; j < 8; j += 4) {
            float4 v; v.x=acc[i][j]; v.y=acc[i][j+1]; v.z=acc[i][j+2]; v.w=acc[i][j+3];
            *(float4*)(op + j) = v;
        }
    }
}

// ---------------- combined bias ----------------------------------------------
__global__ void bias_comb(const float* __restrict__ w_fuse,
                          const float* __restrict__ b_out,
                          const float* __restrict__ b_fuse) {
    int c = blockIdx.x, e = threadIdx.x;
    __shared__ float bo[DD];
    bo[e] = b_out[c*DD + e];
    __syncthreads();
    float s = b_fuse[e];
    const float* wf = w_fuse + (size_t)e * DD;
    #pragma unroll 4
    for (int t = 0; t < DD; t++) s = fmaf(wf[t], bo[t], s);
    g_bc[c*DD + e] = s;
}

// ---------------- attention (one CTA per (c,b)) -------------------------------
__global__ __launch_bounds__(256)
void attn_kernel() {
    const int cb = blockIdx.x;              // 0..607
    const int c  = cb / BB;
    __shared__ float Qs[CC*DD];             // 19 KB
    __shared__ float S[CC][368];            // 27.3 KB
    const int tid = threadIdx.x;

    const float* Qg = g_Q  + (size_t)cb * CC * DD;
    const float* Kg = g_K  + (size_t)cb * NP * DD;
    const float* Vg = g_V  + (size_t)cb * NP * DD;
    float*       Og = g_AO + (size_t)cb * CC * DD;

    for (int i = tid; i < CC*DD; i += 256) Qs[i] = Qg[i];
    __syncthreads();

    const float scale = 0.17677669529663687f;   // 1/sqrt(32)

    for (int h = 0; h < HH; h++) {
        const int hoff = h * HDIM;
        // --- scores + mask ---
        for (int k = tid; k < NP; k += 256) {
            float kr[HDIM];
            const float* kp = Kg + (size_t)k * DD + hoff;
            #pragma unroll
            for (int d = 0; d < HDIM; d += 4) *(float4*)&kr[d] = *(const float4*)(kp + d);
            int ki = k / CC, kj = k % CC;
            for (int j = 0; j < CC; j++) {
                const float* qp = &Qs[j*DD + hoff];
                float s = 0.f;
                #pragma unroll
                for (int d = 0; d < HDIM; d++) s = fmaf(kr[d], qp[d], s);
                bool ok = (ki == c) | (kj == c) | (ki == j) | (kj == j);
                S[j][k] = ok ? s * scale : -1e30f;
            }
        }
        __syncthreads();
        // --- softmax, one warp per row ---
        {
            int w = tid >> 5, lane = tid & 31;
            for (int j = w; j < CC; j += 8) {
                float mx = -1e30f;
                for (int k = lane; k < NP; k += 32) mx = fmaxf(mx, S[j][k]);
                #pragma unroll
                for (int o = 16; o; o >>= 1) mx = fmaxf(mx, __shfl_xor_sync(~0u, mx, o));
                float sum = 0.f;
                for (int k = lane; k < NP; k += 32) {
                    float e = __expf(S[j][k] - mx);
                    S[j][k] = e; sum += e;
                }
                #pragma unroll
                for (int o = 16; o; o >>= 1) sum += __shfl_xor_sync(~0u, sum, o);
                float inv = 1.f / sum;
                for (int k = lane; k < NP; k += 32) S[j][k] *= inv;
            }
        }
        __syncthreads();
        // --- P @ V : lane = head-dim, group = query set ---
        {
            int d = tid & 31, jg = tid >> 5;
            int j0 = jg, j1 = jg + 8, j2 = jg + 16;
            float o0 = 0.f, o1 = 0.f, o2 = 0.f;
            for (int k = 0; k < NP; k++) {
                float v = Vg[(size_t)k * DD + hoff + d];
                o0 = fmaf(S[j0][k], v, o0);
                o1 = fmaf(S[j1][k], v, o1);
                if (j2 < CC) o2 = fmaf(S[j2][k], v, o2);
            }
            Og[j0*DD + hoff + d] = o0;
            Og[j1*DD + hoff + d] = o1;
            if (j2 < CC) Og[j2*DD + hoff + d] = o2;
        }
        __syncthreads();
    }
}

// ---------------- out-proj + fuse + residual ----------------------------------
// grid (5, 2, 19): y[b, c*19+j] = AO[c,b,j] @ Mc[c]^T + bc[c] + x[b, c*19+j]
__global__ __launch_bounds__(256, 2)
void out_fuse(const float* __restrict__ x, float* __restrict__ y) {
    const int c  = blockIdx.z;
    const int m0 = blockIdx.x * 128;
    const int n0 = blockIdx.y * 128;
    __shared__ float As[8][128];
    __shared__ float Bs[8][128];
    const int tid   = threadIdx.x;
    const int ldRow = tid >> 1;
    const int ldCol = (tid & 1) << 2;

    int am = m0 + ldRow; if (am > MQ - 1) am = MQ - 1;
    const float* Ap = g_AO + ((size_t)c*MQ + am) * DD + ldCol;
    const float* Bp = g_Mc + ((size_t)c*DD + n0 + ldRow) * DD + ldCol;

    const int ty = tid >> 4, tx = tid & 15;
    float acc[8][8];
    #pragma unroll
    for (int i = 0; i < 8; i++)
        #pragma unroll
        for (int j = 0; j < 8; j++) acc[i][j] = 0.f;

    for (int kt = 0; kt < DD; kt += 8) {
        float4 a = *(const float4*)(Ap + kt);
        float4 b = *(const float4*)(Bp + kt);
        As[ldCol+0][ldRow]=a.x; As[ldCol+1][ldRow]=a.y;
        As[ldCol+2][ldRow]=a.z; As[ldCol+3][ldRow]=a.w;
        Bs[ldCol+0][ldRow]=b.x; Bs[ldCol+1][ldRow]=b.y;
        Bs[ldCol+2][ldRow]=b.z; Bs[ldCol+3][ldRow]=b.w;
        __syncthreads();
        #pragma unroll
        for (int k = 0; k < 8; k++) {
            float ra[8], rb[8];
            *(float4*)&ra[0] = *(const float4*)&As[k][ty*8];
            *(float4*)&ra[4] = *(const float4*)&As[k][ty*8+4];
            *(float4*)&rb[0] = *(const float4*)&Bs[k][tx*8];
            *(float4*)&rb[4] = *(const float4*)&Bs[k][tx*8+4];
            #pragma unroll
            for (int i = 0; i < 8; i++)
                #pragma unroll
                for (int j = 0; j < 8; j++)
                    acc[i][j] = fmaf(ra[i], rb[j], acc[i][j]);
        }
        __syncthreads();
    }

    const float* bcp = g_bc + c*DD + n0 + tx*8;
    float bv[8];
    #pragma unroll
    for (int j = 0; j < 8; j++) bv[j] = bcp[j];

    #pragma unroll
    for (int i = 0; i < 8; i++) {
        int m = m0 + ty*8 + i;
        if (m >= MQ) break;
        int bb = m / CC, j = m % CC;
        size_t row = (size_t)bb * NP + c * CC + j;
        float*       op = y + row*DD + n0 + tx*8;
        const float* xp = x + row*DD + n0 + tx*8;
        #pragma unroll
        for (int jj = 0; jj < 8; jj += 4) {
            float4 xv = *(const float4*)(xp + jj);
            float4 v;
            v.x = acc[i][jj+0] + bv[jj+0] + xv.x;
            v.y = acc[i][jj+1] + bv[jj+1] + xv.y;
            v.z = acc[i][jj+2] + bv[jj+2] + xv.z;
            v.w = acc[i][jj+3] + bv[jj+3] + xv.w;
            *(float4*)(op + jj) = v;
        }
    }
}

// ---------------- launch -------------------------------------------------------
extern "C" void kernel_launch(void* const* d_in, const int* in_sizes, int n_in,
                              void* d_out, int out_size) {
    const float* x      = (const float*)d_in[0];
    const float* w_in   = (const float*)d_in[1];
    const float* b_in   = (const float*)d_in[2];
    const float* w_out  = (const float*)d_in[3];
    const float* b_out  = (const float*)d_in[4];
    const float* w_fuse = (const float*)d_in[5];
    const float* b_fuse = (const float*)d_in[6];
    float* y = (float*)d_out;

    dim3 gkv((MX + 127) / 128, 4, CC);
    gemm_kv<<<gkv, 256>>>(x, w_in, b_in);

    dim3 gq((MQ + 127) / 128, 2, CC);
    gemm_q<<<gq, 256>>>(x, w_in, b_in);

    dim3 gc(2, 2, CC);
    gemm_comb<<<gc, 256>>>(w_fuse, w_out);
    bias_comb<<<CC, DD>>>(w_fuse, b_out, b_fuse);

    attn_kernel<<<CC*BB, 256>>>();

    out_fuse<<<gq, 256>>>(x, y);
}

// round 2
// speedup vs baseline: 1.4312x; 1.4312x over previous
#include <cuda_runtime.h>
#include <cuda_bf16.h>
#include <cstdint>

#define CC 19
#define NP 361
#define DD 256
#define BB 32
#define HH 8
#define HDIM 32
#define MX (BB*NP)   // 11552
#define MQ (BB*CC)   // 608
#define NKV 512
#define NTOT (CC*NKV) // 9728

// ---------------- scratch (device globals: no allocations allowed) ----------
__device__ float g_K[(size_t)CC*BB*NP*DD];   // [c][b][pos][e]
__device__ float g_V[(size_t)CC*BB*NP*DD];
__device__ float g_Q[(size_t)CC*BB*CC*DD];   // [c][b][j][e]
__device__ float g_AO[(size_t)CC*BB*CC*DD];
__device__ float g_Mc[(size_t)CC*DD*DD];     // combined w_fuse @ w_out[c]
__device__ float g_bc[(size_t)CC*DD];        // combined bias

// bf16 split operands for tensor-core KV GEMM
__device__ __nv_bfloat16 g_xh[(size_t)MX*DD];
__device__ __nv_bfloat16 g_xl[(size_t)MX*DD];
__device__ __nv_bfloat16 g_wh[(size_t)CC*768*DD];
__device__ __nv_bfloat16 g_wl[(size_t)CC*768*DD];

// ---------------- fp32 -> bf16 hi/lo split -----------------------------------
__global__ void split_bf16(const float* __restrict__ src,
                           __nv_bfloat16* __restrict__ h,
                           __nv_bfloat16* __restrict__ l, int n4) {
    int i = blockIdx.x * 256 + threadIdx.x;
    if (i >= n4) return;
    float4 v = ((const float4*)src)[i];
    __nv_bfloat16 h0 = __float2bfloat16(v.x);
    __nv_bfloat16 h1 = __float2bfloat16(v.y);
    __nv_bfloat16 h2 = __float2bfloat16(v.z);
    __nv_bfloat16 h3 = __float2bfloat16(v.w);
    __nv_bfloat162 hh0 = {h0, h1}, hh1 = {h2, h3};
    __nv_bfloat162 ll0 = {__float2bfloat16(v.x - __bfloat162float(h0)),
                          __float2bfloat16(v.y - __bfloat162float(h1))};
    __nv_bfloat162 ll1 = {__float2bfloat16(v.z - __bfloat162float(h2)),
                          __float2bfloat16(v.w - __bfloat162float(h3))};
    ((__nv_bfloat162*)h)[i*2+0] = hh0;
    ((__nv_bfloat162*)h)[i*2+1] = hh1;
    ((__nv_bfloat162*)l)[i*2+0] = ll0;
    ((__nv_bfloat162*)l)[i*2+1] = ll1;
}

// ---------------- bf16x3 tensor-core KV GEMM ---------------------------------
// C(11552 x 9728) = X(11552x256) @ Wkv^T, per-channel weight blocks on N.
#define KT_STEPS 16          // 256 / 16
#define ROWPAD 24            // 16 bf16 + 8 pad (48B rows, conflict-free)

__device__ __forceinline__ void mma16816(float* d, const uint32_t* a, const uint32_t* b) {
    asm volatile(
        "mma.sync.aligned.m16n8k16.row.col.f32.bf16.bf16.f32 "
        "{%0,%1,%2,%3}, {%4,%5,%6,%7}, {%8,%9}, {%0,%1,%2,%3};"
        : "+f"(d[0]), "+f"(d[1]), "+f"(d[2]), "+f"(d[3])
        : "r"(a[0]), "r"(a[1]), "r"(a[2]), "r"(a[3]), "r"(b[0]), "r"(b[1]));
}

__device__ __forceinline__ void cp16(uint32_t smem_addr, const void* gptr) {
    asm volatile("cp.async.cg.shared.global [%0], [%1], 16;\n"
                 :: "r"(smem_addr), "l"(gptr));
}

__global__ __launch_bounds__(256)
void gemm_kv_mma(const float* __restrict__ b_in) {
    const int m0  = blockIdx.x * 128;
    const int n0g = blockIdx.y * 128;
    const int c   = n0g / NKV;
    const int e0  = n0g % NKV;

    __shared__ __nv_bfloat16 sm[2][4][128*ROWPAD];  // 49152 B

    const int tid  = threadIdx.x;
    const int warp = tid >> 5, lane = tid & 31;
    const int wm = (warp >> 2) * 64;
    const int wn = (warp & 3) * 32;
    const int qr = lane >> 2, qc = lane & 3;

    // loader mapping: one 16B chunk per thread per array
    const int lrow = tid >> 1;
    const int lchk = tid & 1;
    int am = m0 + lrow; if (am > MX-1) am = MX-1;
    const __nv_bfloat16* gxh = g_xh + (size_t)am * DD + lchk*8;
    const __nv_bfloat16* gxl = g_xl + (size_t)am * DD + lchk*8;
    const size_t wr = ((size_t)c*768 + 256 + e0 + lrow) * DD + lchk*8;
    const __nv_bfloat16* gwh = g_wh + wr;
    const __nv_bfloat16* gwl = g_wl + wr;
    const uint32_t so = (uint32_t)(lrow*ROWPAD + lchk*8) * 2;  // byte offset in one array

    uint32_t sbase = (uint32_t)__cvta_generic_to_shared(&sm[0][0][0]);
    const uint32_t ARRB = 128*ROWPAD*2;  // bytes per array
    const uint32_t STGB = 4*ARRB;        // bytes per stage

    auto issue = [&](int kt, int stage) {
        uint32_t s0 = sbase + stage*STGB + so;
        int koff = kt * 16;
        cp16(s0 + 0*ARRB, gxh + koff);
        cp16(s0 + 1*ARRB, gxl + koff);
        cp16(s0 + 2*ARRB, gwh + koff);
        cp16(s0 + 3*ARRB, gwl + koff);
        asm volatile("cp.async.commit_group;");
    };

    float acc[4][4][4];
    #pragma unroll
    for (int i = 0; i < 4; i++)
        #pragma unroll
        for (int j = 0; j < 4; j++)
            #pragma unroll
            for (int k = 0; k < 4; k++) acc[i][j][k] = 0.f;

    issue(0, 0);
    issue(1, 1);

    for (int kt = 0; kt < KT_STEPS; kt++) {
        if (kt + 1 < KT_STEPS) asm volatile("cp.async.wait_group 1;");
        else                   asm volatile("cp.async.wait_group 0;");
        __syncthreads();

        const int st = kt & 1;
        const __nv_bfloat16* Ah = sm[st][0];
        const __nv_bfloat16* Al = sm[st][1];
        const __nv_bfloat16* Bh = sm[st][2];
        const __nv_bfloat16* Bl = sm[st][3];

        uint32_t ah[4][4], al[4][4], bh[4][2], bl[4][2];
        #pragma unroll
        for (int ms = 0; ms < 4; ms++) {
            int r0 = wm + ms*16 + qr;
            ah[ms][0] = *(const uint32_t*)&Ah[(r0  )*ROWPAD + qc*2    ];
            ah[ms][1] = *(const uint32_t*)&Ah[(r0+8)*ROWPAD + qc*2    ];
            ah[ms][2] = *(const uint32_t*)&Ah[(r0  )*ROWPAD + qc*2 + 8];
            ah[ms][3] = *(const uint32_t*)&Ah[(r0+8)*ROWPAD + qc*2 + 8];
            al[ms][0] = *(const uint32_t*)&Al[(r0  )*ROWPAD + qc*2    ];
            al[ms][1] = *(const uint32_t*)&Al[(r0+8)*ROWPAD + qc*2    ];
            al[ms][2] = *(const uint32_t*)&Al[(r0  )*ROWPAD + qc*2 + 8];
            al[ms][3] = *(const uint32_t*)&Al[(r0+8)*ROWPAD + qc*2 + 8];
        }
        #pragma unroll
        for (int ns = 0; ns < 4; ns++) {
            int r0 = wn + ns*8 + qr;
            bh[ns][0] = *(const uint32_t*)&Bh[r0*ROWPAD + qc*2    ];
            bh[ns][1] = *(const uint32_t*)&Bh[r0*ROWPAD + qc*2 + 8];
            bl[ns][0] = *(const uint32_t*)&Bl[r0*ROWPAD + qc*2    ];
            bl[ns][1] = *(const uint32_t*)&Bl[r0*ROWPAD + qc*2 + 8];
        }
        #pragma unroll
        for (int ms = 0; ms < 4; ms++)
            #pragma unroll
            for (int ns = 0; ns < 4; ns++) {
                mma16816(acc[ms][ns], ah[ms], bh[ns]);
                mma16816(acc[ms][ns], ah[ms], bl[ns]);
                mma16816(acc[ms][ns], al[ms], bh[ns]);
            }
        __syncthreads();
        if (kt + 2 < KT_STEPS) issue(kt + 2, st);
    }

    // epilogue: +bias, scatter to g_K / g_V
    #pragma unroll
    for (int ns = 0; ns < 4; ns++) {
        int e = e0 + wn + ns*8 + qc*2;
        float b0 = b_in[c*768 + 256 + e];
        float b1 = b_in[c*768 + 256 + e + 1];
        float* base = (e < 256) ? g_K : g_V;
        int col = (e < 256) ? e : e - 256;
        #pragma unroll
        for (int ms = 0; ms < 4; ms++) {
            int gm0 = m0 + wm + ms*16 + qr;
            #pragma unroll
            for (int half = 0; half < 2; half++) {
                int gm = gm0 + half*8;
                if (gm >= MX) continue;
                int bb = gm / NP, pos = gm % NP;
                float2 v;
                v.x = acc[ms][ns][half*2+0] + b0;
                v.y = acc[ms][ns][half*2+1] + b1;
                *(float2*)(base + (((size_t)c*BB + bb)*NP + pos)*DD + col) = v;
            }
        }
    }
}

// ---------------- Q projection GEMM (fp32 SIMT) --------------------------------
__global__ __launch_bounds__(256, 2)
void gemm_q(const float* __restrict__ x, const float* __restrict__ w_in,
            const float* __restrict__ b_in) {
    const int c  = blockIdx.z;
    const int m0 = blockIdx.x * 128;
    const int n0 = blockIdx.y * 128;
    __shared__ float As[8][128];
    __shared__ float Bs[8][128];
    const int tid   = threadIdx.x;
    const int ldRow = tid >> 1;
    const int ldCol = (tid & 1) << 2;

    int am = m0 + ldRow; if (am > MQ - 1) am = MQ - 1;
    int xrow = (am / CC) * NP + c * CC + (am % CC);
    const float* Ap = x + (size_t)xrow * DD + ldCol;
    const float* Bp = w_in + ((size_t)c * 768 + n0 + ldRow) * DD + ldCol;

    const int ty = tid >> 4, tx = tid & 15;
    float acc[8][8];
    #pragma unroll
    for (int i = 0; i < 8; i++)
        #pragma unroll
        for (int j = 0; j < 8; j++) acc[i][j] = 0.f;

    for (int kt = 0; kt < DD; kt += 8) {
        float4 a = *(const float4*)(Ap + kt);
        float4 b = *(const float4*)(Bp + kt);
        As[ldCol+0][ldRow]=a.x; As[ldCol+1][ldRow]=a.y;
        As[ldCol+2][ldRow]=a.z; As[ldCol+3][ldRow]=a.w;
        Bs[ldCol+0][ldRow]=b.x; Bs[ldCol+1][ldRow]=b.y;
        Bs[ldCol+2][ldRow]=b.z; Bs[ldCol+3][ldRow]=b.w;
        __syncthreads();
        #pragma unroll
        for (int k = 0; k < 8; k++) {
            float ra[8], rb[8];
            *(float4*)&ra[0] = *(const float4*)&As[k][ty*8];
            *(float4*)&ra[4] = *(const float4*)&As[k][ty*8+4];
            *(float4*)&rb[0] = *(const float4*)&Bs[k][tx*8];
            *(float4*)&rb[4] = *(const float4*)&Bs[k][tx*8+4];
            #pragma unroll
            for (int i = 0; i < 8; i++)
                #pragma unroll
                for (int j = 0; j < 8; j++)
                    acc[i][j] = fmaf(ra[i], rb[j], acc[i][j]);
        }
        __syncthreads();
    }

    const float* bi = b_in + c*768 + n0 + tx*8;
    float bv[8];
    #pragma unroll
    for (int j = 0; j < 8; j++) bv[j] = bi[j];

    #pragma unroll
    for (int i = 0; i < 8; i++) {
        int m = m0 + ty*8 + i;
        if (m >= MQ) break;
        float* op = g_Q + ((size_t)c*MQ + m)*DD + n0 + tx*8;
        #pragma unroll
        for (int j = 0; j < 8; j += 4) {
            float4 v;
            v.x = acc[i][j+0] + bv[j+0];
            v.y = acc[i][j+1] + bv[j+1];
            v.z = acc[i][j+2] + bv[j+2];
            v.w = acc[i][j+3] + bv[j+3];
            *(float4*)(op + j) = v;
        }
    }
}

// ---------------- combined weight: Mc[c] = w_fuse @ w_out[c] -----------------
__global__ __launch_bounds__(256, 2)
void gemm_comb(const float* __restrict__ w_fuse, const float* __restrict__ w_out) {
    const int c  = blockIdx.z;
    const int m0 = blockIdx.x * 128;
    const int n0 = blockIdx.y * 128;
    __shared__ float As[8][128];
    __shared__ float Bs[8][128];
    const int tid  = threadIdx.x;
    const int aRow = tid >> 1, aCol = (tid & 1) << 2;
    const int bK   = tid >> 5, bN = (tid & 31) << 2;

    const float* Ap = w_fuse + (size_t)(m0 + aRow) * DD + aCol;
    const float* Bbase = w_out + (size_t)c * DD * DD;

    const int ty = tid >> 4, tx = tid & 15;
    float acc[8][8];
    #pragma unroll
    for (int i = 0; i < 8; i++)
        #pragma unroll
        for (int j = 0; j < 8; j++) acc[i][j] = 0.f;

    for (int kt = 0; kt < DD; kt += 8) {
        float4 a = *(const float4*)(Ap + kt);
        float4 b = *(const float4*)(Bbase + (size_t)(kt + bK) * DD + n0 + bN);
        As[aCol+0][aRow]=a.x; As[aCol+1][aRow]=a.y;
        As[aCol+2][aRow]=a.z; As[aCol+3][aRow]=a.w;
        *(float4*)&Bs[bK][bN] = b;
        __syncthreads();
        #pragma unroll
        for (int k = 0; k < 8; k++) {
            float ra[8], rb[8];
            *(float4*)&ra[0] = *(const float4*)&As[k][ty*8];
            *(float4*)&ra[4] = *(const float4*)&As[k][ty*8+4];
            *(float4*)&rb[0] = *(const float4*)&Bs[k][tx*8];
            *(float4*)&rb[4] = *(const float4*)&Bs[k][tx*8+4];
            #pragma unroll
            for (int i = 0; i < 8; i++)
                #pragma unroll
                for (int j = 0; j < 8; j++)
                    acc[i][j] = fmaf(ra[i], rb[j], acc[i][j]);
        }
        __syncthreads();
    }

    #pragma unroll
    for (int i = 0; i < 8; i++) {
        int m = m0 + ty*8 + i;
        float* op = g_Mc + ((size_t)c*DD + m)*DD + n0 + tx*8;
        #pragma unroll
        for (int j = 0; j < 8; j += 4) {
            float4 v; v.x=acc[i][j]; v.y=acc[i][j+1]; v.z=acc[i][j+2]; v.w=acc[i][j+3];
            *(float4*)(op + j) = v;
        }
    }
}

// ---------------- combined bias ----------------------------------------------
__global__ void bias_comb(const float* __restrict__ w_fuse,
                          const float* __restrict__ b_out,
                          const float* __restrict__ b_fuse) {
    int c = blockIdx.x, e = threadIdx.x;
    __shared__ float bo[DD];
    bo[e] = b_out[c*DD + e];
    __syncthreads();
    float s = b_fuse[e];
    const float* wf = w_fuse + (size_t)e * DD;
    #pragma unroll 4
    for (int t = 0; t < DD; t++) s = fmaf(wf[t], bo[t], s);
    g_bc[c*DD + e] = s;
}

// ---------------- attention (one CTA per (c,b)) -------------------------------
__global__ __launch_bounds__(256)
void attn_kernel() {
    const int cb = blockIdx.x;              // 0..607
    const int c  = cb / BB;
    __shared__ float Qs[CC*DD];
    __shared__ float S[CC][368];
    const int tid = threadIdx.x;

    const float* Qg = g_Q  + (size_t)cb * CC * DD;
    const float* Kg = g_K  + (size_t)cb * NP * DD;
    const float* Vg = g_V  + (size_t)cb * NP * DD;
    float*       Og = g_AO + (size_t)cb * CC * DD;

    for (int i = tid; i < CC*DD; i += 256) Qs[i] = Qg[i];
    __syncthreads();

    const float scale = 0.17677669529663687f;

    for (int h = 0; h < HH; h++) {
        const int hoff = h * HDIM;
        for (int k = tid; k < NP; k += 256) {
            float kr[HDIM];
            const float* kp = Kg + (size_t)k * DD + hoff;
            #pragma unroll
            for (int d = 0; d < HDIM; d += 4) *(float4*)&kr[d] = *(const float4*)(kp + d);
            int ki = k / CC, kj = k % CC;
            for (int j = 0; j < CC; j++) {
                const float* qp = &Qs[j*DD + hoff];
                float s = 0.f;
                #pragma unroll
                for (int d = 0; d < HDIM; d++) s = fmaf(kr[d], qp[d], s);
                bool ok = (ki == c) | (kj == c) | (ki == j) | (kj == j);
                S[j][k] = ok ? s * scale : -1e30f;
            }
        }
        __syncthreads();
        {
            int w = tid >> 5, lane = tid & 31;
            for (int j = w; j < CC; j += 8) {
                float mx = -1e30f;
                for (int k = lane; k < NP; k += 32) mx = fmaxf(mx, S[j][k]);
                #pragma unroll
                for (int o = 16; o; o >>= 1) mx = fmaxf(mx, __shfl_xor_sync(~0u, mx, o));
                float sum = 0.f;
                for (int k = lane; k < NP; k += 32) {
                    float e = __expf(S[j][k] - mx);
                    S[j][k] = e; sum += e;
                }
                #pragma unroll
                for (int o = 16; o; o >>= 1) sum += __shfl_xor_sync(~0u, sum, o);
                float inv = 1.f / sum;
                for (int k = lane; k < NP; k += 32) S[j][k] *= inv;
            }
        }
        __syncthreads();
        {
            int d = tid & 31, jg = tid >> 5;
            int j0 = jg, j1 = jg + 8, j2 = jg + 16;
            float o0 = 0.f, o1 = 0.f, o2 = 0.f;
            for (int k = 0; k < NP; k++) {
                float v = Vg[(size_t)k * DD + hoff + d];
                o0 = fmaf(S[j0][k], v, o0);
                o1 = fmaf(S[j1][k], v, o1);
                if (j2 < CC) o2 = fmaf(S[j2][k], v, o2);
            }
            Og[j0*DD + hoff + d] = o0;
            Og[j1*DD + hoff + d] = o1;
            if (j2 < CC) Og[j2*DD + hoff + d] = o2;
        }
        __syncthreads();
    }
}

// ---------------- out-proj + fuse + residual ----------------------------------
__global__ __launch_bounds__(256, 2)
void out_fuse(const float* __restrict__ x, float* __restrict__ y) {
    const int c  = blockIdx.z;
    const int m0 = blockIdx.x * 128;
    const int n0 = blockIdx.y * 128;
    __shared__ float As[8][128];
    __shared__ float Bs[8][128];
    const int tid   = threadIdx.x;
    const int ldRow = tid >> 1;
    const int ldCol = (tid & 1) << 2;

    int am = m0 + ldRow; if (am > MQ - 1) am = MQ - 1;
    const float* Ap = g_AO + ((size_t)c*MQ + am) * DD + ldCol;
    const float* Bp = g_Mc + ((size_t)c*DD + n0 + ldRow) * DD + ldCol;

    const int ty = tid >> 4, tx = tid & 15;
    float acc[8][8];
    #pragma unroll
    for (int i = 0; i < 8; i++)
        #pragma unroll
        for (int j = 0; j < 8; j++) acc[i][j] = 0.f;

    for (int kt = 0; kt < DD; kt += 8) {
        float4 a = *(const float4*)(Ap + kt);
        float4 b = *(const float4*)(Bp + kt);
        As[ldCol+0][ldRow]=a.x; As[ldCol+1][ldRow]=a.y;
        As[ldCol+2][ldRow]=a.z; As[ldCol+3][ldRow]=a.w;
        Bs[ldCol+0][ldRow]=b.x; Bs[ldCol+1][ldRow]=b.y;
        Bs[ldCol+2][ldRow]=b.z; Bs[ldCol+3][ldRow]=b.w;
        __syncthreads();
        #pragma unroll
        for (int k = 0; k < 8; k++) {
            float ra[8], rb[8];
            *(float4*)&ra[0] = *(const float4*)&As[k][ty*8];
            *(float4*)&ra[4] = *(const float4*)&As[k][ty*8+4];
            *(float4*)&rb[0] = *(const float4*)&Bs[k][tx*8];
            *(float4*)&rb[4] = *(const float4*)&Bs[k][tx*8+4];
            #pragma unroll
            for (int i = 0; i < 8; i++)
                #pragma unroll
                for (int j = 0; j < 8; j++)
                    acc[i][j] = fmaf(ra[i], rb[j], acc[i][j]);
        }
        __syncthreads();
    }

    const float* bcp = g_bc + c*DD + n0 + tx*8;
    float bv[8];
    #pragma unroll
    for (int j = 0; j < 8; j++) bv[j] = bcp[j];

    #pragma unroll
    for (int i = 0; i < 8; i++) {
        int m = m0 + ty*8 + i;
        if (m >= MQ) break;
        int bb = m / CC, j = m % CC;
        size_t row = (size_t)bb * NP + c * CC + j;
        float*       op = y + row*DD + n0 + tx*8;
        const float* xp = x + row*DD + n0 + tx*8;
        #pragma unroll
        for (int jj = 0; jj < 8; jj += 4) {
            float4 xv = *(const float4*)(xp + jj);
            float4 v;
            v.x = acc[i][jj+0] + bv[jj+0] + xv.x;
            v.y = acc[i][jj+1] + bv[jj+1] + xv.y;
            v.z = acc[i][jj+2] + bv[jj+2] + xv.z;
            v.w = acc[i][jj+3] + bv[jj+3] + xv.w;
            *(float4*)(op + jj) = v;
        }
    }
}

// ---------------- launch -------------------------------------------------------
extern "C" void kernel_launch(void* const* d_in, const int* in_sizes, int n_in,
                              void* d_out, int out_size) {
    const float* x      = (const float*)d_in[0];
    const float* w_in   = (const float*)d_in[1];
    const float* b_in   = (const float*)d_in[2];
    const float* w_out  = (const float*)d_in[3];
    const float* b_out  = (const float*)d_in[4];
    const float* w_fuse = (const float*)d_in[5];
    const float* b_fuse = (const float*)d_in[6];
    float* y = (float*)d_out;

    __nv_bfloat16 *xh, *xl, *wh, *wl;
    cudaGetSymbolAddress((void**)&xh, g_xh);
    cudaGetSymbolAddress((void**)&xl, g_xl);
    cudaGetSymbolAddress((void**)&wh, g_wh);
    cudaGetSymbolAddress((void**)&wl, g_wl);

    {
        int n4 = (MX*DD)/4;
        split_bf16<<<(n4 + 255)/256, 256>>>(x, xh, xl, n4);
    }
    {
        int n4 = (CC*768*DD)/4;
        split_bf16<<<(n4 + 255)/256, 256>>>(w_in, wh, wl, n4);
    }

    dim3 gkv((MX + 127) / 128, NTOT / 128);   // (91, 76)
    gemm_kv_mma<<<gkv, 256>>>(b_in);

    dim3 gq((MQ + 127) / 128, 2, CC);
    gemm_q<<<gq, 256>>>(x, w_in, b_in);

    dim3 gc(2, 2, CC);
    gemm_comb<<<gc, 256>>>(w_fuse, w_out);
    bias_comb<<<CC, DD>>>(w_fuse, b_out, b_fuse);

    attn_kernel<<<CC*BB, 256>>>();

    out_fuse<<<gq, 256>>>(x, y);
}

// round 4
// speedup vs baseline: 1.4469x; 1.0110x over previous
#include <cuda_runtime.h>
#include <cuda_bf16.h>
#include <cstdint>

#define CC 19
#define NP 361
#define DD 256
#define BB 32
#define HH 8
#define HDIM 32
#define MX (BB*NP)   // 11552
#define MQ (BB*CC)   // 608
#define NKV 512
#define NTOT (CC*NKV) // 9728

// ---------------- scratch (device globals: no allocations allowed) ----------
__device__ float g_K[(size_t)CC*BB*NP*DD];   // [c][b][pos][e]
__device__ float g_V[(size_t)CC*BB*NP*DD];
__device__ float g_Q[(size_t)CC*BB*CC*DD];   // [c][b][j][e]
__device__ float g_AO[(size_t)CC*BB*CC*DD];
__device__ float g_Mc[(size_t)CC*DD*DD];     // combined w_fuse @ w_out[c]
__device__ float g_bc[(size_t)CC*DD];        // combined bias

// bf16 split operands for tensor-core KV GEMM
__device__ __nv_bfloat16 g_xh[(size_t)MX*DD];
__device__ __nv_bfloat16 g_xl[(size_t)MX*DD];
__device__ __nv_bfloat16 g_wh[(size_t)CC*768*DD];
__device__ __nv_bfloat16 g_wl[(size_t)CC*768*DD];

// ---------------- fp32 -> bf16 hi/lo split -----------------------------------
__global__ void split_bf16(const float* __restrict__ src,
                           __nv_bfloat16* __restrict__ h,
                           __nv_bfloat16* __restrict__ l, int n4) {
    int i = blockIdx.x * 256 + threadIdx.x;
    if (i >= n4) return;
    float4 v = ((const float4*)src)[i];
    __nv_bfloat16 h0 = __float2bfloat16(v.x);
    __nv_bfloat16 h1 = __float2bfloat16(v.y);
    __nv_bfloat16 h2 = __float2bfloat16(v.z);
    __nv_bfloat16 h3 = __float2bfloat16(v.w);
    __nv_bfloat162 hh0 = {h0, h1}, hh1 = {h2, h3};
    __nv_bfloat162 ll0 = {__float2bfloat16(v.x - __bfloat162float(h0)),
                          __float2bfloat16(v.y - __bfloat162float(h1))};
    __nv_bfloat162 ll1 = {__float2bfloat16(v.z - __bfloat162float(h2)),
                          __float2bfloat16(v.w - __bfloat162float(h3))};
    ((__nv_bfloat162*)h)[i*2+0] = hh0;
    ((__nv_bfloat162*)h)[i*2+1] = hh1;
    ((__nv_bfloat162*)l)[i*2+0] = ll0;
    ((__nv_bfloat162*)l)[i*2+1] = ll1;
}

// ---------------- HMMA helpers -------------------------------------------------
__device__ __forceinline__ void mma16816(float* d, const uint32_t* a, const uint32_t* b) {
    asm volatile(
        "mma.sync.aligned.m16n8k16.row.col.f32.bf16.bf16.f32 "
        "{%0,%1,%2,%3}, {%4,%5,%6,%7}, {%8,%9}, {%0,%1,%2,%3};"
        : "+f"(d[0]), "+f"(d[1]), "+f"(d[2]), "+f"(d[3])
        : "r"(a[0]), "r"(a[1]), "r"(a[2]), "r"(a[3]), "r"(b[0]), "r"(b[1]));
}
__device__ __forceinline__ void ldsm4(uint32_t* r, uint32_t addr) {
    asm volatile("ldmatrix.sync.aligned.m8n8.x4.shared.b16 {%0,%1,%2,%3}, [%4];"
                 : "=r"(r[0]), "=r"(r[1]), "=r"(r[2]), "=r"(r[3]) : "r"(addr));
}
__device__ __forceinline__ void cp16(uint32_t saddr, const void* g) {
    asm volatile("cp.async.cg.shared.global [%0], [%1], 16;\n" :: "r"(saddr), "l"(g));
}
__device__ __forceinline__ uint32_t smem_u32(const void* p) {
    uint32_t a;
    asm("{ .reg .u64 t; cvta.to.shared.u64 t, %1; cvt.u32.u64 %0, t; }" : "=r"(a) : "l"(p));
    return a;
}

// ---------------- bf16x3 tensor-core KV GEMM (mma.sync + ldmatrix) -------------
// C(11552 x 9728) = X(11552x256) @ Wkv^T. CTA tile 128x128, k-step 16, 3 stages.
#define ROWB 48                       // bytes per smem row (32B data + 16B pad)
#define ARRB (128*ROWB)               // 6144 B per operand array
#define STGB (4*ARRB)                 // 24576 B per stage
#define KV_SMEM (3*STGB)              // 73728 B

__global__ __launch_bounds__(256)
void gemm_kv_mma(const float* __restrict__ b_in) {
    extern __shared__ char smraw[];
    const uint32_t sbase = smem_u32(smraw);

    const int tid  = threadIdx.x;
    const int warp = tid >> 5, lane = tid & 31;
    const int m0   = blockIdx.x * 128;
    const int n0g  = blockIdx.y * 128;
    const int c    = n0g / NKV;
    const int e0   = n0g % NKV;

    const int wm = (warp >> 2) * 64;
    const int wn = (warp & 3) * 32;

    // ldmatrix lane offsets (within one operand array)
    uint32_t aoff[4], boff[2];
    {
        int mr = (lane & 7) + ((lane >> 3) & 1) * 8;
        int kb = (lane >> 4) * 16;
        #pragma unroll
        for (int ms = 0; ms < 4; ms++) aoff[ms] = (uint32_t)((wm + ms*16 + mr) * ROWB + kb);
        int nr  = (lane & 7) + ((lane >> 4) & 1) * 8;
        int kbb = ((lane >> 3) & 1) * 16;
        #pragma unroll
        for (int n2 = 0; n2 < 2; n2++) boff[n2] = (uint32_t)((wn + n2*16 + nr) * ROWB + kbb);
    }

    // loader mapping: thread t -> row t/2, 16B chunk t%2, one cp16 per array
    const int lrow = tid >> 1;
    const int lchk = tid & 1;
    int am = m0 + lrow; if (am > MX-1) am = MX-1;
    const __nv_bfloat16* pxh = g_xh + (size_t)am * DD + lchk*8;
    const __nv_bfloat16* pxl = g_xl + (size_t)am * DD + lchk*8;
    const size_t wrow = ((size_t)c * 768 + 256 + e0 + lrow) * DD + lchk*8;
    const __nv_bfloat16* pwh = g_wh + wrow;
    const __nv_bfloat16* pwl = g_wl + wrow;
    const uint32_t so = (uint32_t)(lrow*ROWB + lchk*16);

    auto issue = [&](int kt) {
        uint32_t s0 = sbase + (uint32_t)(kt % 3) * STGB + so;
        int k0 = kt * 16;
        cp16(s0 + 0*ARRB, pxh + k0);
        cp16(s0 + 1*ARRB, pxl + k0);
        cp16(s0 + 2*ARRB, pwh + k0);
        cp16(s0 + 3*ARRB, pwl + k0);
        asm volatile("cp.async.commit_group;");
    };

    float acc[4][4][4];
    #pragma unroll
    for (int i = 0; i < 4; i++)
        #pragma unroll
        for (int j = 0; j < 4; j++)
            #pragma unroll
            for (int k = 0; k < 4; k++) acc[i][j][k] = 0.f;

    issue(0); issue(1); issue(2);

    for (int kt = 0; kt < 16; kt++) {
        if (kt < 14) asm volatile("cp.async.wait_group 2;");
        else         asm volatile("cp.async.wait_group 0;");
        __syncthreads();

        const uint32_t base = sbase + (uint32_t)(kt % 3) * STGB;
        uint32_t ah[4][4], al[4][4], bh[4][2], bl[4][2];
        #pragma unroll
        for (int ms = 0; ms < 4; ms++) {
            ldsm4(ah[ms], base + 0*ARRB + aoff[ms]);
            ldsm4(al[ms], base + 1*ARRB + aoff[ms]);
        }
        #pragma unroll
        for (int n2 = 0; n2 < 2; n2++) {
            ldsm4(&bh[n2*2][0], base + 2*ARRB + boff[n2]);
            ldsm4(&bl[n2*2][0], base + 3*ARRB + boff[n2]);
        }
        __syncthreads();                 // all warps done reading this stage
        if (kt + 3 < 16) issue(kt + 3);  // refill same buffer, overlaps MMAs

        #pragma unroll
        for (int ms = 0; ms < 4; ms++)
            #pragma unroll
            for (int ns = 0; ns < 4; ns++) {
                mma16816(acc[ms][ns], ah[ms], bh[ns]);
                mma16816(acc[ms][ns], ah[ms], bl[ns]);
                mma16816(acc[ms][ns], al[ms], bh[ns]);
            }
    }

    // epilogue: +bias, scatter to g_K / g_V
    const int qr = lane >> 2, qc = lane & 3;
    #pragma unroll
    for (int ns = 0; ns < 4; ns++) {
        int e = e0 + wn + ns*8 + qc*2;
        float b0 = b_in[c*768 + 256 + e];
        float b1 = b_in[c*768 + 256 + e + 1];
        float* base = (e < 256) ? g_K : g_V;
        int col = (e < 256) ? e : e - 256;
        #pragma unroll
        for (int ms = 0; ms < 4; ms++) {
            int gm0 = m0 + wm + ms*16 + qr;
            #pragma unroll
            for (int half = 0; half < 2; half++) {
                int gm = gm0 + half*8;
                if (gm >= MX) continue;
                int bb = gm / NP, pos = gm % NP;
                float2 v;
                v.x = acc[ms][ns][half*2+0] + b0;
                v.y = acc[ms][ns][half*2+1] + b1;
                *(float2*)(base + (((size_t)c*BB + bb)*NP + pos)*DD + col) = v;
            }
        }
    }
}

// ---------------- Q projection GEMM (fp32 SIMT) --------------------------------
__global__ __launch_bounds__(256, 2)
void gemm_q(const float* __restrict__ x, const float* __restrict__ w_in,
            const float* __restrict__ b_in) {
    const int c  = blockIdx.z;
    const int m0 = blockIdx.x * 128;
    const int n0 = blockIdx.y * 128;
    __shared__ float As[8][128];
    __shared__ float Bs[8][128];
    const int tid   = threadIdx.x;
    const int ldRow = tid >> 1;
    const int ldCol = (tid & 1) << 2;

    int am = m0 + ldRow; if (am > MQ - 1) am = MQ - 1;
    int xrow = (am / CC) * NP + c * CC + (am % CC);
    const float* Ap = x + (size_t)xrow * DD + ldCol;
    const float* Bp = w_in + ((size_t)c * 768 + n0 + ldRow) * DD + ldCol;

    const int ty = tid >> 4, tx = tid & 15;
    float acc[8][8];
    #pragma unroll
    for (int i = 0; i < 8; i++)
        #pragma unroll
        for (int j = 0; j < 8; j++) acc[i][j] = 0.f;

    for (int kt = 0; kt < DD; kt += 8) {
        float4 a = *(const float4*)(Ap + kt);
        float4 b = *(const float4*)(Bp + kt);
        As[ldCol+0][ldRow]=a.x; As[ldCol+1][ldRow]=a.y;
        As[ldCol+2][ldRow]=a.z; As[ldCol+3][ldRow]=a.w;
        Bs[ldCol+0][ldRow]=b.x; Bs[ldCol+1][ldRow]=b.y;
        Bs[ldCol+2][ldRow]=b.z; Bs[ldCol+3][ldRow]=b.w;
        __syncthreads();
        #pragma unroll
        for (int k = 0; k < 8; k++) {
            float ra[8], rb[8];
            *(float4*)&ra[0] = *(const float4*)&As[k][ty*8];
            *(float4*)&ra[4] = *(const float4*)&As[k][ty*8+4];
            *(float4*)&rb[0] = *(const float4*)&Bs[k][tx*8];
            *(float4*)&rb[4] = *(const float4*)&Bs[k][tx*8+4];
            #pragma unroll
            for (int i = 0; i < 8; i++)
                #pragma unroll
                for (int j = 0; j < 8; j++)
                    acc[i][j] = fmaf(ra[i], rb[j], acc[i][j]);
        }
        __syncthreads();
    }

    const float* bi = b_in + c*768 + n0 + tx*8;
    float bv[8];
    #pragma unroll
    for (int j = 0; j < 8; j++) bv[j] = bi[j];

    #pragma unroll
    for (int i = 0; i < 8; i++) {
        int m = m0 + ty*8 + i;
        if (m >= MQ) break;
        float* op = g_Q + ((size_t)c*MQ + m)*DD + n0 + tx*8;
        #pragma unroll
        for (int j = 0; j < 8; j += 4) {
            float4 v;
            v.x = acc[i][j+0] + bv[j+0];
            v.y = acc[i][j+1] + bv[j+1];
            v.z = acc[i][j+2] + bv[j+2];
            v.w = acc[i][j+3] + bv[j+3];
            *(float4*)(op + j) = v;
        }
    }
}

// ---------------- combined weight: Mc[c] = w_fuse @ w_out[c] -----------------
__global__ __launch_bounds__(256, 2)
void gemm_comb(const float* __restrict__ w_fuse, const float* __restrict__ w_out) {
    const int c  = blockIdx.z;
    const int m0 = blockIdx.x * 128;
    const int n0 = blockIdx.y * 128;
    __shared__ float As[8][128];
    __shared__ float Bs[8][128];
    const int tid  = threadIdx.x;
    const int aRow = tid >> 1, aCol = (tid & 1) << 2;
    const int bK   = tid >> 5, bN = (tid & 31) << 2;

    const float* Ap = w_fuse + (size_t)(m0 + aRow) * DD + aCol;
    const float* Bbase = w_out + (size_t)c * DD * DD;

    const int ty = tid >> 4, tx = tid & 15;
    float acc[8][8];
    #pragma unroll
    for (int i = 0; i < 8; i++)
        #pragma unroll
        for (int j = 0; j < 8; j++) acc[i][j] = 0.f;

    for (int kt = 0; kt < DD; kt += 8) {
        float4 a = *(const float4*)(Ap + kt);
        float4 b = *(const float4*)(Bbase + (size_t)(kt + bK) * DD + n0 + bN);
        As[aCol+0][aRow]=a.x; As[aCol+1][aRow]=a.y;
        As[aCol+2][aRow]=a.z; As[aCol+3][aRow]=a.w;
        *(float4*)&Bs[bK][bN] = b;
        __syncthreads();
        #pragma unroll
        for (int k = 0; k < 8; k++) {
            float ra[8], rb[8];
            *(float4*)&ra[0] = *(const float4*)&As[k][ty*8];
            *(float4*)&ra[4] = *(const float4*)&As[k][ty*8+4];
            *(float4*)&rb[0] = *(const float4*)&Bs[k][tx*8];
            *(float4*)&rb[4] = *(const float4*)&Bs[k][tx*8+4];
            #pragma unroll
            for (int i = 0; i < 8; i++)
                #pragma unroll
                for (int j = 0; j < 8; j++)
                    acc[i][j] = fmaf(ra[i], rb[j], acc[i][j]);
        }
        __syncthreads();
    }

    #pragma unroll
    for (int i = 0; i < 8; i++) {
        int m = m0 + ty*8 + i;
        float* op = g_Mc + ((size_t)c*DD + m)*DD + n0 + tx*8;
        #pragma unroll
        for (int j = 0; j < 8; j += 4) {
            float4 v; v.x=acc[i][j]; v.y=acc[i][j+1]; v.z=acc[i][j+2]; v.w=acc[i][j+3];
            *(float4*)(op + j) = v;
        }
    }
}

// ---------------- combined bias (warp per output) ------------------------------
__global__ void bias_comb(const float* __restrict__ w_fuse,
                          const float* __restrict__ b_out,
                          const float* __restrict__ b_fuse) {
    int c = blockIdx.x;
    int e = blockIdx.y * 8 + (threadIdx.x >> 5);
    int lane = threadIdx.x & 31;
    const float* wf = w_fuse + (size_t)e * DD;
    const float* bo = b_out + c * DD;
    float s = 0.f;
    #pragma unroll
    for (int i = 0; i < 8; i++) s = fmaf(wf[lane + i*32], bo[lane + i*32], s);
    #pragma unroll
    for (int o = 16; o; o >>= 1) s += __shfl_xor_sync(~0u, s, o);
    if (lane == 0) g_bc[c*DD + e] = s + b_fuse[e];
}

// ---------------- attention (one CTA per (c,b)) -------------------------------
__global__ __launch_bounds__(256)
void attn_kernel() {
    const int cb = blockIdx.x;              // 0..607
    const int c  = cb / BB;
    __shared__ float Qs[CC*DD];
    __shared__ float S[CC][368];
    const int tid = threadIdx.x;

    const float* Qg = g_Q  + (size_t)cb * CC * DD;
    const float* Kg = g_K  + (size_t)cb * NP * DD;
    const float* Vg = g_V  + (size_t)cb * NP * DD;
    float*       Og = g_AO + (size_t)cb * CC * DD;

    for (int i = tid; i < CC*DD; i += 256) Qs[i] = Qg[i];
    __syncthreads();

    const float scale = 0.17677669529663687f;

    for (int h = 0; h < HH; h++) {
        const int hoff = h * HDIM;
        for (int k = tid; k < NP; k += 256) {
            float kr[HDIM];
            const float* kp = Kg + (size_t)k * DD + hoff;
            #pragma unroll
            for (int d = 0; d < HDIM; d += 4) *(float4*)&kr[d] = *(const float4*)(kp + d);
            int ki = k / CC, kj = k % CC;
            for (int j = 0; j < CC; j++) {
                const float* qp = &Qs[j*DD + hoff];
                float s = 0.f;
                #pragma unroll
                for (int d = 0; d < HDIM; d++) s = fmaf(kr[d], qp[d], s);
                bool ok = (ki == c) | (kj == c) | (ki == j) | (kj == j);
                S[j][k] = ok ? s * scale : -1e30f;
            }
        }
        __syncthreads();
        {
            int w = tid >> 5, lane = tid & 31;
            for (int j = w; j < CC; j += 8) {
                float mx = -1e30f;
                for (int k = lane; k < NP; k += 32) mx = fmaxf(mx, S[j][k]);
                #pragma unroll
                for (int o = 16; o; o >>= 1) mx = fmaxf(mx, __shfl_xor_sync(~0u, mx, o));
                float sum = 0.f;
                for (int k = lane; k < NP; k += 32) {
                    float e = __expf(S[j][k] - mx);
                    S[j][k] = e; sum += e;
                }
                #pragma unroll
                for (int o = 16; o; o >>= 1) sum += __shfl_xor_sync(~0u, sum, o);
                float inv = 1.f / sum;
                for (int k = lane; k < NP; k += 32) S[j][k] *= inv;
            }
        }
        __syncthreads();
        {
            int d = tid & 31, jg = tid >> 5;
            int j0 = jg, j1 = jg + 8, j2 = jg + 16;
            float o0 = 0.f, o1 = 0.f, o2 = 0.f;
            for (int k = 0; k < NP; k++) {
                float v = Vg[(size_t)k * DD + hoff + d];
                o0 = fmaf(S[j0][k], v, o0);
                o1 = fmaf(S[j1][k], v, o1);
                if (j2 < CC) o2 = fmaf(S[j2][k], v, o2);
            }
            Og[j0*DD + hoff + d] = o0;
            Og[j1*DD + hoff + d] = o1;
            if (j2 < CC) Og[j2*DD + hoff + d] = o2;
        }
        __syncthreads();
    }
}

// ---------------- out-proj + fuse + residual ----------------------------------
__global__ __launch_bounds__(256, 2)
void out_fuse(const float* __restrict__ x, float* __restrict__ y) {
    const int c  = blockIdx.z;
    const int m0 = blockIdx.x * 128;
    const int n0 = blockIdx.y * 128;
    __shared__ float As[8][128];
    __shared__ float Bs[8][128];
    const int tid   = threadIdx.x;
    const int ldRow = tid >> 1;
    const int ldCol = (tid & 1) << 2;

    int am = m0 + ldRow; if (am > MQ - 1) am = MQ - 1;
    const float* Ap = g_AO + ((size_t)c*MQ + am) * DD + ldCol;
    const float* Bp = g_Mc + ((size_t)c*DD + n0 + ldRow) * DD + ldCol;

    const int ty = tid >> 4, tx = tid & 15;
    float acc[8][8];
    #pragma unroll
    for (int i = 0; i < 8; i++)
        #pragma unroll
        for (int j = 0; j < 8; j++) acc[i][j] = 0.f;

    for (int kt = 0; kt < DD; kt += 8) {
        float4 a = *(const float4*)(Ap + kt);
        float4 b = *(const float4*)(Bp + kt);
        As[ldCol+0][ldRow]=a.x; As[ldCol+1][ldRow]=a.y;
        As[ldCol+2][ldRow]=a.z; As[ldCol+3][ldRow]=a.w;
        Bs[ldCol+0][ldRow]=b.x; Bs[ldCol+1][ldRow]=b.y;
        Bs[ldCol+2][ldRow]=b.z; Bs[ldCol+3][ldRow]=b.w;
        __syncthreads();
        #pragma unroll
        for (int k = 0; k < 8; k++) {
            float ra[8], rb[8];
            *(float4*)&ra[0] = *(const float4*)&As[k][ty*8];
            *(float4*)&ra[4] = *(const float4*)&As[k][ty*8+4];
            *(float4*)&rb[0] = *(const float4*)&Bs[k][tx*8];
            *(float4*)&rb[4] = *(const float4*)&Bs[k][tx*8+4];
            #pragma unroll
            for (int i = 0; i < 8; i++)
                #pragma unroll
                for (int j = 0; j < 8; j++)
                    acc[i][j] = fmaf(ra[i], rb[j], acc[i][j]);
        }
        __syncthreads();
    }

    const float* bcp = g_bc + c*DD + n0 + tx*8;
    float bv[8];
    #pragma unroll
    for (int j = 0; j < 8; j++) bv[j] = bcp[j];

    #pragma unroll
    for (int i = 0; i < 8; i++) {
        int m = m0 + ty*8 + i;
        if (m >= MQ) break;
        int bb = m / CC, j = m % CC;
        size_t row = (size_t)bb * NP + c * CC + j;
        float*       op = y + row*DD + n0 + tx*8;
        const float* xp = x + row*DD + n0 + tx*8;
        #pragma unroll
        for (int jj = 0; jj < 8; jj += 4) {
            float4 xv = *(const float4*)(xp + jj);
            float4 v;
            v.x = acc[i][jj+0] + bv[jj+0] + xv.x;
            v.y = acc[i][jj+1] + bv[jj+1] + xv.y;
            v.z = acc[i][jj+2] + bv[jj+2] + xv.z;
            v.w = acc[i][jj+3] + bv[jj+3] + xv.w;
            *(float4*)(op + jj) = v;
        }
    }
}

// ---------------- launch -------------------------------------------------------
extern "C" void kernel_launch(void* const* d_in, const int* in_sizes, int n_in,
                              void* d_out, int out_size) {
    const float* x      = (const float*)d_in[0];
    const float* w_in   = (const float*)d_in[1];
    const float* b_in   = (const float*)d_in[2];
    const float* w_out  = (const float*)d_in[3];
    const float* b_out  = (const float*)d_in[4];
    const float* w_fuse = (const float*)d_in[5];
    const float* b_fuse = (const float*)d_in[6];
    float* y = (float*)d_out;

    __nv_bfloat16 *xh, *xl, *wh, *wl;
    cudaGetSymbolAddress((void**)&xh, g_xh);
    cudaGetSymbolAddress((void**)&xl, g_xl);
    cudaGetSymbolAddress((void**)&wh, g_wh);
    cudaGetSymbolAddress((void**)&wl, g_wl);

    cudaFuncSetAttribute(gemm_kv_mma, cudaFuncAttributeMaxDynamicSharedMemorySize, KV_SMEM);

    {
        int n4 = (MX*DD)/4;
        split_bf16<<<(n4 + 255)/256, 256>>>(x, xh, xl, n4);
    }
    {
        int n4 = (CC*768*DD)/4;
        split_bf16<<<(n4 + 255)/256, 256>>>(w_in, wh, wl, n4);
    }

    dim3 gkv((MX + 127) / 128, NTOT / 128);   // (91, 76)
    gemm_kv_mma<<<gkv, 256, KV_SMEM>>>(b_in);

    dim3 gq((MQ + 127) / 128, 2, CC);
    gemm_q<<<gq, 256>>>(x, w_in, b_in);

    dim3 gc(2, 2, CC);
    gemm_comb<<<gc, 256>>>(w_fuse, w_out);
    bias_comb<<<dim3(CC, DD/8), 256>>>(w_fuse, b_out, b_fuse);

    attn_kernel<<<CC*BB, 256>>>();

    out_fuse<<<gq, 256>>>(x, y);
}

// round 5
// speedup vs baseline: 1.6164x; 1.1172x over previous
#include <cuda_runtime.h>
#include <cuda_bf16.h>
#include <cstdint>

#define CC 19
#define NP 361
#define DD 256
#define BB 32
#define HH 8
#define HDIM 32
#define MX (BB*NP)   // 11552
#define MQ (BB*CC)   // 608
#define NKV 512
#define NTOT (CC*NKV) // 9728

// ---------------- scratch (device globals: no allocations allowed) ----------
__device__ float g_K[(size_t)CC*BB*NP*DD];   // [c][b][pos][e]
__device__ float g_V[(size_t)CC*BB*NP*DD];
__device__ float g_Q[(size_t)CC*BB*CC*DD];   // [c][b][j][e]
__device__ float g_AO[(size_t)CC*BB*CC*DD];
__device__ float g_Mc[(size_t)CC*DD*DD];     // combined w_fuse @ w_out[c]
__device__ float g_bc[(size_t)CC*DD];        // combined bias

// bf16 split operands for tensor-core KV GEMM
__device__ __nv_bfloat16 g_xh[(size_t)MX*DD];
__device__ __nv_bfloat16 g_xl[(size_t)MX*DD];
__device__ __nv_bfloat16 g_wh[(size_t)CC*768*DD];
__device__ __nv_bfloat16 g_wl[(size_t)CC*768*DD];

// ---------------- fp32 -> bf16 hi/lo split -----------------------------------
__global__ void split_bf16(const float* __restrict__ src,
                           __nv_bfloat16* __restrict__ h,
                           __nv_bfloat16* __restrict__ l, int n4) {
    int i = blockIdx.x * 256 + threadIdx.x;
    if (i >= n4) return;
    float4 v = ((const float4*)src)[i];
    __nv_bfloat16 h0 = __float2bfloat16(v.x);
    __nv_bfloat16 h1 = __float2bfloat16(v.y);
    __nv_bfloat16 h2 = __float2bfloat16(v.z);
    __nv_bfloat16 h3 = __float2bfloat16(v.w);
    __nv_bfloat162 hh0 = {h0, h1}, hh1 = {h2, h3};
    __nv_bfloat162 ll0 = {__float2bfloat16(v.x - __bfloat162float(h0)),
                          __float2bfloat16(v.y - __bfloat162float(h1))};
    __nv_bfloat162 ll1 = {__float2bfloat16(v.z - __bfloat162float(h2)),
                          __float2bfloat16(v.w - __bfloat162float(h3))};
    ((__nv_bfloat162*)h)[i*2+0] = hh0;
    ((__nv_bfloat162*)h)[i*2+1] = hh1;
    ((__nv_bfloat162*)l)[i*2+0] = ll0;
    ((__nv_bfloat162*)l)[i*2+1] = ll1;
}

// ---------------- HMMA helpers -------------------------------------------------
__device__ __forceinline__ void mma16816(float* d, const uint32_t* a, const uint32_t* b) {
    asm volatile(
        "mma.sync.aligned.m16n8k16.row.col.f32.bf16.bf16.f32 "
        "{%0,%1,%2,%3}, {%4,%5,%6,%7}, {%8,%9}, {%0,%1,%2,%3};"
        : "+f"(d[0]), "+f"(d[1]), "+f"(d[2]), "+f"(d[3])
        : "r"(a[0]), "r"(a[1]), "r"(a[2]), "r"(a[3]), "r"(b[0]), "r"(b[1]));
}
__device__ __forceinline__ void ldsm4(uint32_t* r, uint32_t addr) {
    asm volatile("ldmatrix.sync.aligned.m8n8.x4.shared.b16 {%0,%1,%2,%3}, [%4];"
                 : "=r"(r[0]), "=r"(r[1]), "=r"(r[2]), "=r"(r[3]) : "r"(addr));
}
__device__ __forceinline__ void cp16(uint32_t saddr, const void* g) {
    asm volatile("cp.async.cg.shared.global [%0], [%1], 16;\n" :: "r"(saddr), "l"(g));
}
__device__ __forceinline__ uint32_t smem_u32(const void* p) {
    uint32_t a;
    asm("{ .reg .u64 t; cvta.to.shared.u64 t, %1; cvt.u32.u64 %0, t; }" : "=r"(a) : "l"(p));
    return a;
}

// ---------------- bf16x3 tensor-core KV GEMM (single-sync pipeline) ------------
// C(11552 x 9728) = X(11552x256) @ Wkv^T. CTA tile 128x128, k-step 16, 3 stages.
#define ROWB 48                       // bytes per smem row (32B data + 16B pad)
#define ARRB (128*ROWB)               // 6144 B per operand array
#define STGB (4*ARRB)                 // 24576 B per stage
#define KV_SMEM (3*STGB)              // 73728 B

__global__ __launch_bounds__(256)
void gemm_kv_mma(const float* __restrict__ b_in) {
    extern __shared__ char smraw[];
    const uint32_t sbase = smem_u32(smraw);

    const int tid  = threadIdx.x;
    const int warp = tid >> 5, lane = tid & 31;
    const int m0   = blockIdx.x * 128;
    const int n0g  = blockIdx.y * 128;
    const int c    = n0g / NKV;
    const int e0   = n0g % NKV;

    const int wm = (warp >> 2) * 64;
    const int wn = (warp & 3) * 32;

    // ldmatrix lane offsets (within one operand array)
    uint32_t aoff[4], boff[2];
    {
        int mr = (lane & 7) + ((lane >> 3) & 1) * 8;
        int kb = (lane >> 4) * 16;
        #pragma unroll
        for (int ms = 0; ms < 4; ms++) aoff[ms] = (uint32_t)((wm + ms*16 + mr) * ROWB + kb);
        int nr  = (lane & 7) + ((lane >> 4) & 1) * 8;
        int kbb = ((lane >> 3) & 1) * 16;
        #pragma unroll
        for (int n2 = 0; n2 < 2; n2++) boff[n2] = (uint32_t)((wn + n2*16 + nr) * ROWB + kbb);
    }

    // loader mapping: thread t -> row t/2, 16B chunk t%2, one cp16 per array
    const int lrow = tid >> 1;
    const int lchk = tid & 1;
    int am = m0 + lrow; if (am > MX-1) am = MX-1;
    const __nv_bfloat16* pxh = g_xh + (size_t)am * DD + lchk*8;
    const __nv_bfloat16* pxl = g_xl + (size_t)am * DD + lchk*8;
    const size_t wrow = ((size_t)c * 768 + 256 + e0 + lrow) * DD + lchk*8;
    const __nv_bfloat16* pwh = g_wh + wrow;
    const __nv_bfloat16* pwl = g_wl + wrow;
    const uint32_t so = (uint32_t)(lrow*ROWB + lchk*16);

    auto issue = [&](int kt) {
        uint32_t s0 = sbase + (uint32_t)(kt % 3) * STGB + so;
        int k0 = kt * 16;
        cp16(s0 + 0*ARRB, pxh + k0);
        cp16(s0 + 1*ARRB, pxl + k0);
        cp16(s0 + 2*ARRB, pwh + k0);
        cp16(s0 + 3*ARRB, pwl + k0);
        asm volatile("cp.async.commit_group;");
    };

    // double-buffered fragments
    uint32_t ah[2][4][4], al[2][4][4], bh[2][4][2], bl[2][4][2];
    auto ldfrags = [&](int buf, uint32_t base) {
        #pragma unroll
        for (int ms = 0; ms < 4; ms++) {
            ldsm4(ah[buf][ms], base + 0*ARRB + aoff[ms]);
            ldsm4(al[buf][ms], base + 1*ARRB + aoff[ms]);
        }
        #pragma unroll
        for (int n2 = 0; n2 < 2; n2++) {
            ldsm4(&bh[buf][n2*2][0], base + 2*ARRB + boff[n2]);
            ldsm4(&bl[buf][n2*2][0], base + 3*ARRB + boff[n2]);
        }
    };

    float acc[4][4][4];
    #pragma unroll
    for (int i = 0; i < 4; i++)
        #pragma unroll
        for (int j = 0; j < 4; j++)
            #pragma unroll
            for (int k = 0; k < 4; k++) acc[i][j][k] = 0.f;

    issue(0); issue(1); issue(2);
    asm volatile("cp.async.wait_group 2;");
    __syncthreads();
    ldfrags(0, sbase + 0*STGB);

    #pragma unroll
    for (int kt = 0; kt < 16; kt++) {
        const int cur = kt & 1, nxt = cur ^ 1;
        // stage kt+1 readiness (own groups), then CTA-wide visibility + reuse barrier
        if (kt < 14)       asm volatile("cp.async.wait_group 1;");
        else if (kt == 14) asm volatile("cp.async.wait_group 0;");
        __syncthreads();
        if (kt + 3 < 16) issue(kt + 3);                       // refill stage kt%3
        if (kt + 1 < 16) ldfrags(nxt, sbase + (uint32_t)((kt+1)%3)*STGB);

        #pragma unroll
        for (int ms = 0; ms < 4; ms++)
            #pragma unroll
            for (int ns = 0; ns < 4; ns++) {
                mma16816(acc[ms][ns], ah[cur][ms], bh[cur][ns]);
                mma16816(acc[ms][ns], ah[cur][ms], bl[cur][ns]);
                mma16816(acc[ms][ns], al[cur][ms], bh[cur][ns]);
            }
    }

    // epilogue: +bias, scatter to g_K / g_V
    const int qr = lane >> 2, qc = lane & 3;
    #pragma unroll
    for (int ns = 0; ns < 4; ns++) {
        int e = e0 + wn + ns*8 + qc*2;
        float b0 = b_in[c*768 + 256 + e];
        float b1 = b_in[c*768 + 256 + e + 1];
        float* base = (e < 256) ? g_K : g_V;
        int col = (e < 256) ? e : e - 256;
        #pragma unroll
        for (int ms = 0; ms < 4; ms++) {
            int gm0 = m0 + wm + ms*16 + qr;
            #pragma unroll
            for (int half = 0; half < 2; half++) {
                int gm = gm0 + half*8;
                if (gm >= MX) continue;
                int bb = gm / NP, pos = gm % NP;
                float2 v;
                v.x = acc[ms][ns][half*2+0] + b0;
                v.y = acc[ms][ns][half*2+1] + b1;
                *(float2*)(base + (((size_t)c*BB + bb)*NP + pos)*DD + col) = v;
            }
        }
    }
}

// ---------------- Q projection GEMM (fp32 SIMT) --------------------------------
__global__ __launch_bounds__(256, 2)
void gemm_q(const float* __restrict__ x, const float* __restrict__ w_in,
            const float* __restrict__ b_in) {
    const int c  = blockIdx.z;
    const int m0 = blockIdx.x * 128;
    const int n0 = blockIdx.y * 128;
    __shared__ float As[8][128];
    __shared__ float Bs[8][128];
    const int tid   = threadIdx.x;
    const int ldRow = tid >> 1;
    const int ldCol = (tid & 1) << 2;

    int am = m0 + ldRow; if (am > MQ - 1) am = MQ - 1;
    int xrow = (am / CC) * NP + c * CC + (am % CC);
    const float* Ap = x + (size_t)xrow * DD + ldCol;
    const float* Bp = w_in + ((size_t)c * 768 + n0 + ldRow) * DD + ldCol;

    const int ty = tid >> 4, tx = tid & 15;
    float acc[8][8];
    #pragma unroll
    for (int i = 0; i < 8; i++)
        #pragma unroll
        for (int j = 0; j < 8; j++) acc[i][j] = 0.f;

    for (int kt = 0; kt < DD; kt += 8) {
        float4 a = *(const float4*)(Ap + kt);
        float4 b = *(const float4*)(Bp + kt);
        As[ldCol+0][ldRow]=a.x; As[ldCol+1][ldRow]=a.y;
        As[ldCol+2][ldRow]=a.z; As[ldCol+3][ldRow]=a.w;
        Bs[ldCol+0][ldRow]=b.x; Bs[ldCol+1][ldRow]=b.y;
        Bs[ldCol+2][ldRow]=b.z; Bs[ldCol+3][ldRow]=b.w;
        __syncthreads();
        #pragma unroll
        for (int k = 0; k < 8; k++) {
            float ra[8], rb[8];
            *(float4*)&ra[0] = *(const float4*)&As[k][ty*8];
            *(float4*)&ra[4] = *(const float4*)&As[k][ty*8+4];
            *(float4*)&rb[0] = *(const float4*)&Bs[k][tx*8];
            *(float4*)&rb[4] = *(const float4*)&Bs[k][tx*8+4];
            #pragma unroll
            for (int i = 0; i < 8; i++)
                #pragma unroll
                for (int j = 0; j < 8; j++)
                    acc[i][j] = fmaf(ra[i], rb[j], acc[i][j]);
        }
        __syncthreads();
    }

    const float* bi = b_in + c*768 + n0 + tx*8;
    float bv[8];
    #pragma unroll
    for (int j = 0; j < 8; j++) bv[j] = bi[j];

    #pragma unroll
    for (int i = 0; i < 8; i++) {
        int m = m0 + ty*8 + i;
        if (m >= MQ) break;
        float* op = g_Q + ((size_t)c*MQ + m)*DD + n0 + tx*8;
        #pragma unroll
        for (int j = 0; j < 8; j += 4) {
            float4 v;
            v.x = acc[i][j+0] + bv[j+0];
            v.y = acc[i][j+1] + bv[j+1];
            v.z = acc[i][j+2] + bv[j+2];
            v.w = acc[i][j+3] + bv[j+3];
            *(float4*)(op + j) = v;
        }
    }
}

// ---------------- combined weight: Mc[c] = w_fuse @ w_out[c] -----------------
__global__ __launch_bounds__(256, 2)
void gemm_comb(const float* __restrict__ w_fuse, const float* __restrict__ w_out) {
    const int c  = blockIdx.z;
    const int m0 = blockIdx.x * 128;
    const int n0 = blockIdx.y * 128;
    __shared__ float As[8][128];
    __shared__ float Bs[8][128];
    const int tid  = threadIdx.x;
    const int aRow = tid >> 1, aCol = (tid & 1) << 2;
    const int bK   = tid >> 5, bN = (tid & 31) << 2;

    const float* Ap = w_fuse + (size_t)(m0 + aRow) * DD + aCol;
    const float* Bbase = w_out + (size_t)c * DD * DD;

    const int ty = tid >> 4, tx = tid & 15;
    float acc[8][8];
    #pragma unroll
    for (int i = 0; i < 8; i++)
        #pragma unroll
        for (int j = 0; j < 8; j++) acc[i][j] = 0.f;

    for (int kt = 0; kt < DD; kt += 8) {
        float4 a = *(const float4*)(Ap + kt);
        float4 b = *(const float4*)(Bbase + (size_t)(kt + bK) * DD + n0 + bN);
        As[aCol+0][aRow]=a.x; As[aCol+1][aRow]=a.y;
        As[aCol+2][aRow]=a.z; As[aCol+3][aRow]=a.w;
        *(float4*)&Bs[bK][bN] = b;
        __syncthreads();
        #pragma unroll
        for (int k = 0; k < 8; k++) {
            float ra[8], rb[8];
            *(float4*)&ra[0] = *(const float4*)&As[k][ty*8];
            *(float4*)&ra[4] = *(const float4*)&As[k][ty*8+4];
            *(float4*)&rb[0] = *(const float4*)&Bs[k][tx*8];
            *(float4*)&rb[4] = *(const float4*)&Bs[k][tx*8+4];
            #pragma unroll
            for (int i = 0; i < 8; i++)
                #pragma unroll
                for (int j = 0; j < 8; j++)
                    acc[i][j] = fmaf(ra[i], rb[j], acc[i][j]);
        }
        __syncthreads();
    }

    #pragma unroll
    for (int i = 0; i < 8; i++) {
        int m = m0 + ty*8 + i;
        float* op = g_Mc + ((size_t)c*DD + m)*DD + n0 + tx*8;
        #pragma unroll
        for (int j = 0; j < 8; j += 4) {
            float4 v; v.x=acc[i][j]; v.y=acc[i][j+1]; v.z=acc[i][j+2]; v.w=acc[i][j+3];
            *(float4*)(op + j) = v;
        }
    }
}

// ---------------- combined bias (warp per output) ------------------------------
__global__ void bias_comb(const float* __restrict__ w_fuse,
                          const float* __restrict__ b_out,
                          const float* __restrict__ b_fuse) {
    int c = blockIdx.x;
    int e = blockIdx.y * 8 + (threadIdx.x >> 5);
    int lane = threadIdx.x & 31;
    const float* wf = w_fuse + (size_t)e * DD;
    const float* bo = b_out + c * DD;
    float s = 0.f;
    #pragma unroll
    for (int i = 0; i < 8; i++) s = fmaf(wf[lane + i*32], bo[lane + i*32], s);
    #pragma unroll
    for (int o = 16; o; o >>= 1) s += __shfl_xor_sync(~0u, s, o);
    if (lane == 0) g_bc[c*DD + e] = s + b_fuse[e];
}

// ---------------- attention (one CTA per (c,b)) -------------------------------
__global__ __launch_bounds__(256)
void attn_kernel() {
    const int cb = blockIdx.x;              // 0..607
    const int c  = cb / BB;
    __shared__ float Qs[CC*DD];
    __shared__ float S[CC][368];
    const int tid = threadIdx.x;

    const float* Qg = g_Q  + (size_t)cb * CC * DD;
    const float* Kg = g_K  + (size_t)cb * NP * DD;
    const float* Vg = g_V  + (size_t)cb * NP * DD;
    float*       Og = g_AO + (size_t)cb * CC * DD;

    for (int i = tid; i < CC*DD; i += 256) Qs[i] = Qg[i];
    __syncthreads();

    const float scale = 0.17677669529663687f;

    for (int h = 0; h < HH; h++) {
        const int hoff = h * HDIM;
        for (int k = tid; k < NP; k += 256) {
            float kr[HDIM];
            const float* kp = Kg + (size_t)k * DD + hoff;
            #pragma unroll
            for (int d = 0; d < HDIM; d += 4) *(float4*)&kr[d] = *(const float4*)(kp + d);
            int ki = k / CC, kj = k % CC;
            for (int j = 0; j < CC; j++) {
                const float* qp = &Qs[j*DD + hoff];
                float s = 0.f;
                #pragma unroll
                for (int d = 0; d < HDIM; d++) s = fmaf(kr[d], qp[d], s);
                bool ok = (ki == c) | (kj == c) | (ki == j) | (kj == j);
                S[j][k] = ok ? s * scale : -1e30f;
            }
        }
        __syncthreads();
        {
            int w = tid >> 5, lane = tid & 31;
            for (int j = w; j < CC; j += 8) {
                float mx = -1e30f;
                for (int k = lane; k < NP; k += 32) mx = fmaxf(mx, S[j][k]);
                #pragma unroll
                for (int o = 16; o; o >>= 1) mx = fmaxf(mx, __shfl_xor_sync(~0u, mx, o));
                float sum = 0.f;
                for (int k = lane; k < NP; k += 32) {
                    float e = __expf(S[j][k] - mx);
                    S[j][k] = e; sum += e;
                }
                #pragma unroll
                for (int o = 16; o; o >>= 1) sum += __shfl_xor_sync(~0u, sum, o);
                float inv = 1.f / sum;
                for (int k = lane; k < NP; k += 32) S[j][k] *= inv;
            }
        }
        __syncthreads();
        {
            int d = tid & 31, jg = tid >> 5;
            int j0 = jg, j1 = jg + 8, j2 = jg + 16;
            float o0 = 0.f, o1 = 0.f, o2 = 0.f;
            for (int k = 0; k < NP; k++) {
                float v = Vg[(size_t)k * DD + hoff + d];
                o0 = fmaf(S[j0][k], v, o0);
                o1 = fmaf(S[j1][k], v, o1);
                if (j2 < CC) o2 = fmaf(S[j2][k], v, o2);
            }
            Og[j0*DD + hoff + d] = o0;
            Og[j1*DD + hoff + d] = o1;
            if (j2 < CC) Og[j2*DD + hoff + d] = o2;
        }
        __syncthreads();
    }
}

// ---------------- out-proj + fuse + residual ----------------------------------
__global__ __launch_bounds__(256, 2)
void out_fuse(const float* __restrict__ x, float* __restrict__ y) {
    const int c  = blockIdx.z;
    const int m0 = blockIdx.x * 128;
    const int n0 = blockIdx.y * 128;
    __shared__ float As[8][128];
    __shared__ float Bs[8][128];
    const int tid   = threadIdx.x;
    const int ldRow = tid >> 1;
    const int ldCol = (tid & 1) << 2;

    int am = m0 + ldRow; if (am > MQ - 1) am = MQ - 1;
    const float* Ap = g_AO + ((size_t)c*MQ + am) * DD + ldCol;
    const float* Bp = g_Mc + ((size_t)c*DD + n0 + ldRow) * DD + ldCol;

    const int ty = tid >> 4, tx = tid & 15;
    float acc[8][8];
    #pragma unroll
    for (int i = 0; i < 8; i++)
        #pragma unroll
        for (int j = 0; j < 8; j++) acc[i][j] = 0.f;

    for (int kt = 0; kt < DD; kt += 8) {
        float4 a = *(const float4*)(Ap + kt);
        float4 b = *(const float4*)(Bp + kt);
        As[ldCol+0][ldRow]=a.x; As[ldCol+1][ldRow]=a.y;
        As[ldCol+2][ldRow]=a.z; As[ldCol+3][ldRow]=a.w;
        Bs[ldCol+0][ldRow]=b.x; Bs[ldCol+1][ldRow]=b.y;
        Bs[ldCol+2][ldRow]=b.z; Bs[ldCol+3][ldRow]=b.w;
        __syncthreads();
        #pragma unroll
        for (int k = 0; k < 8; k++) {
            float ra[8], rb[8];
            *(float4*)&ra[0] = *(const float4*)&As[k][ty*8];
            *(float4*)&ra[4] = *(const float4*)&As[k][ty*8+4];
            *(float4*)&rb[0] = *(const float4*)&Bs[k][tx*8];
            *(float4*)&rb[4] = *(const float4*)&Bs[k][tx*8+4];
            #pragma unroll
            for (int i = 0; i < 8; i++)
                #pragma unroll
                for (int j = 0; j < 8; j++)
                    acc[i][j] = fmaf(ra[i], rb[j], acc[i][j]);
        }
        __syncthreads();
    }

    const float* bcp = g_bc + c*DD + n0 + tx*8;
    float bv[8];
    #pragma unroll
    for (int j = 0; j < 8; j++) bv[j] = bcp[j];

    #pragma unroll
    for (int i = 0; i < 8; i++) {
        int m = m0 + ty*8 + i;
        if (m >= MQ) break;
        int bb = m / CC, j = m % CC;
        size_t row = (size_t)bb * NP + c * CC + j;
        float*       op = y + row*DD + n0 + tx*8;
        const float* xp = x + row*DD + n0 + tx*8;
        #pragma unroll
        for (int jj = 0; jj < 8; jj += 4) {
            float4 xv = *(const float4*)(xp + jj);
            float4 v;
            v.x = acc[i][jj+0] + bv[jj+0] + xv.x;
            v.y = acc[i][jj+1] + bv[jj+1] + xv.y;
            v.z = acc[i][jj+2] + bv[jj+2] + xv.z;
            v.w = acc[i][jj+3] + bv[jj+3] + xv.w;
            *(float4*)(op + jj) = v;
        }
    }
}

// ---------------- launch -------------------------------------------------------
extern "C" void kernel_launch(void* const* d_in, const int* in_sizes, int n_in,
                              void* d_out, int out_size) {
    const float* x      = (const float*)d_in[0];
    const float* w_in   = (const float*)d_in[1];
    const float* b_in   = (const float*)d_in[2];
    const float* w_out  = (const float*)d_in[3];
    const float* b_out  = (const float*)d_in[4];
    const float* w_fuse = (const float*)d_in[5];
    const float* b_fuse = (const float*)d_in[6];
    float* y = (float*)d_out;

    __nv_bfloat16 *xh, *xl, *wh, *wl;
    cudaGetSymbolAddress((void**)&xh, g_xh);
    cudaGetSymbolAddress((void**)&xl, g_xl);
    cudaGetSymbolAddress((void**)&wh, g_wh);
    cudaGetSymbolAddress((void**)&wl, g_wl);

    cudaFuncSetAttribute(gemm_kv_mma, cudaFuncAttributeMaxDynamicSharedMemorySize, KV_SMEM);

    // launch order chosen so the ncu capture window (launch #4) profiles gemm_kv_mma
    {
        int n4 = (MX*DD)/4;
        split_bf16<<<(n4 + 255)/256, 256>>>(x, xh, xl, n4);                 // 1
    }
    {
        int n4 = (CC*768*DD)/4;
        split_bf16<<<(n4 + 255)/256, 256>>>(w_in, wh, wl, n4);              // 2
    }

    dim3 gq((MQ + 127) / 128, 2, CC);
    gemm_q<<<gq, 256>>>(x, w_in, b_in);                                     // 3

    dim3 gkv((MX + 127) / 128, NTOT / 128);   // (91, 76)
    gemm_kv_mma<<<gkv, 256, KV_SMEM>>>(b_in);                               // 4 (profiled)

    dim3 gc(2, 2, CC);
    gemm_comb<<<gc, 256>>>(w_fuse, w_out);                                  // 5
    bias_comb<<<dim3(CC, DD/8), 256>>>(w_fuse, b_out, b_fuse);              // 6

    attn_kernel<<<CC*BB, 256>>>();                                          // 7

    out_fuse<<<gq, 256>>>(x, y);                                            // 8
}

// round 6
// speedup vs baseline: 1.6629x; 1.0288x over previous
#include <cuda_runtime.h>
#include <cuda_bf16.h>
#include <cstdint>

#define CC 19
#define NP 361
#define DD 256
#define BB 32
#define HH 8
#define HDIM 32
#define MX (BB*NP)   // 11552
#define MQ (BB*CC)   // 608
#define NKV 512
#define NTOT (CC*NKV) // 9728

// ---------------- scratch (device globals: no allocations allowed) ----------
__device__ float g_K[(size_t)CC*BB*NP*DD];   // [c][b][pos][e]
__device__ float g_V[(size_t)CC*BB*NP*DD];
__device__ float g_AO[(size_t)CC*BB*CC*DD];
__device__ float g_Mc[(size_t)CC*DD*DD];     // combined w_fuse @ w_out[c]
__device__ float g_bc[(size_t)CC*DD];        // combined bias

// bf16 split operands for tensor-core KV GEMM
__device__ __nv_bfloat16 g_xh[(size_t)MX*DD];
__device__ __nv_bfloat16 g_xl[(size_t)MX*DD];
__device__ __nv_bfloat16 g_wh[(size_t)CC*768*DD];
__device__ __nv_bfloat16 g_wl[(size_t)CC*768*DD];

// ---------------- fp32 -> bf16 hi/lo split -----------------------------------
__global__ void split_bf16(const float* __restrict__ src,
                           __nv_bfloat16* __restrict__ h,
                           __nv_bfloat16* __restrict__ l, int n4) {
    int i = blockIdx.x * 256 + threadIdx.x;
    if (i >= n4) return;
    float4 v = ((const float4*)src)[i];
    __nv_bfloat16 h0 = __float2bfloat16(v.x);
    __nv_bfloat16 h1 = __float2bfloat16(v.y);
    __nv_bfloat16 h2 = __float2bfloat16(v.z);
    __nv_bfloat16 h3 = __float2bfloat16(v.w);
    __nv_bfloat162 hh0 = {h0, h1}, hh1 = {h2, h3};
    __nv_bfloat162 ll0 = {__float2bfloat16(v.x - __bfloat162float(h0)),
                          __float2bfloat16(v.y - __bfloat162float(h1))};
    __nv_bfloat162 ll1 = {__float2bfloat16(v.z - __bfloat162float(h2)),
                          __float2bfloat16(v.w - __bfloat162float(h3))};
    ((__nv_bfloat162*)h)[i*2+0] = hh0;
    ((__nv_bfloat162*)h)[i*2+1] = hh1;
    ((__nv_bfloat162*)l)[i*2+0] = ll0;
    ((__nv_bfloat162*)l)[i*2+1] = ll1;
}

// ---------------- HMMA helpers -------------------------------------------------
__device__ __forceinline__ void mma16816(float* d, const uint32_t* a, const uint32_t* b) {
    asm volatile(
        "mma.sync.aligned.m16n8k16.row.col.f32.bf16.bf16.f32 "
        "{%0,%1,%2,%3}, {%4,%5,%6,%7}, {%8,%9}, {%0,%1,%2,%3};"
        : "+f"(d[0]), "+f"(d[1]), "+f"(d[2]), "+f"(d[3])
        : "r"(a[0]), "r"(a[1]), "r"(a[2]), "r"(a[3]), "r"(b[0]), "r"(b[1]));
}
__device__ __forceinline__ void ldsm4(uint32_t* r, uint32_t addr) {
    asm volatile("ldmatrix.sync.aligned.m8n8.x4.shared.b16 {%0,%1,%2,%3}, [%4];"
                 : "=r"(r[0]), "=r"(r[1]), "=r"(r[2]), "=r"(r[3]) : "r"(addr));
}
__device__ __forceinline__ void cp16(uint32_t saddr, const void* g) {
    asm volatile("cp.async.cg.shared.global [%0], [%1], 16;\n" :: "r"(saddr), "l"(g));
}
__device__ __forceinline__ uint32_t smem_u32(const void* p) {
    uint32_t a;
    asm("{ .reg .u64 t; cvta.to.shared.u64 t, %1; cvt.u32.u64 %0, t; }" : "=r"(a) : "l"(p));
    return a;
}

// ---------------- bf16x3 tensor-core KV GEMM (single-sync pipeline) ------------
#define ROWB 48
#define ARRB (128*ROWB)
#define STGB (4*ARRB)
#define KV_SMEM (3*STGB)              // 73728 B

__global__ __launch_bounds__(256)
void gemm_kv_mma(const float* __restrict__ b_in) {
    extern __shared__ char smraw[];
    const uint32_t sbase = smem_u32(smraw);

    const int tid  = threadIdx.x;
    const int warp = tid >> 5, lane = tid & 31;
    const int m0   = blockIdx.x * 128;
    const int n0g  = blockIdx.y * 128;
    const int c    = n0g / NKV;
    const int e0   = n0g % NKV;

    const int wm = (warp >> 2) * 64;
    const int wn = (warp & 3) * 32;

    uint32_t aoff[4], boff[2];
    {
        int mr = (lane & 7) + ((lane >> 3) & 1) * 8;
        int kb = (lane >> 4) * 16;
        #pragma unroll
        for (int ms = 0; ms < 4; ms++) aoff[ms] = (uint32_t)((wm + ms*16 + mr) * ROWB + kb);
        int nr  = (lane & 7) + ((lane >> 4) & 1) * 8;
        int kbb = ((lane >> 3) & 1) * 16;
        #pragma unroll
        for (int n2 = 0; n2 < 2; n2++) boff[n2] = (uint32_t)((wn + n2*16 + nr) * ROWB + kbb);
    }

    const int lrow = tid >> 1;
    const int lchk = tid & 1;
    int am = m0 + lrow; if (am > MX-1) am = MX-1;
    const __nv_bfloat16* pxh = g_xh + (size_t)am * DD + lchk*8;
    const __nv_bfloat16* pxl = g_xl + (size_t)am * DD + lchk*8;
    const size_t wrow = ((size_t)c * 768 + 256 + e0 + lrow) * DD + lchk*8;
    const __nv_bfloat16* pwh = g_wh + wrow;
    const __nv_bfloat16* pwl = g_wl + wrow;
    const uint32_t so = (uint32_t)(lrow*ROWB + lchk*16);

    auto issue = [&](int kt) {
        uint32_t s0 = sbase + (uint32_t)(kt % 3) * STGB + so;
        int k0 = kt * 16;
        cp16(s0 + 0*ARRB, pxh + k0);
        cp16(s0 + 1*ARRB, pxl + k0);
        cp16(s0 + 2*ARRB, pwh + k0);
        cp16(s0 + 3*ARRB, pwl + k0);
        asm volatile("cp.async.commit_group;");
    };

    uint32_t ah[2][4][4], al[2][4][4], bh[2][4][2], bl[2][4][2];
    auto ldfrags = [&](int buf, uint32_t base) {
        #pragma unroll
        for (int ms = 0; ms < 4; ms++) {
            ldsm4(ah[buf][ms], base + 0*ARRB + aoff[ms]);
            ldsm4(al[buf][ms], base + 1*ARRB + aoff[ms]);
        }
        #pragma unroll
        for (int n2 = 0; n2 < 2; n2++) {
            ldsm4(&bh[buf][n2*2][0], base + 2*ARRB + boff[n2]);
            ldsm4(&bl[buf][n2*2][0], base + 3*ARRB + boff[n2]);
        }
    };

    float acc[4][4][4];
    #pragma unroll
    for (int i = 0; i < 4; i++)
        #pragma unroll
        for (int j = 0; j < 4; j++)
            #pragma unroll
            for (int k = 0; k < 4; k++) acc[i][j][k] = 0.f;

    issue(0); issue(1); issue(2);
    asm volatile("cp.async.wait_group 2;");
    __syncthreads();
    ldfrags(0, sbase + 0*STGB);

    #pragma unroll
    for (int kt = 0; kt < 16; kt++) {
        const int cur = kt & 1, nxt = cur ^ 1;
        if (kt < 14)       asm volatile("cp.async.wait_group 1;");
        else if (kt == 14) asm volatile("cp.async.wait_group 0;");
        __syncthreads();
        if (kt + 3 < 16) issue(kt + 3);
        if (kt + 1 < 16) ldfrags(nxt, sbase + (uint32_t)((kt+1)%3)*STGB);

        #pragma unroll
        for (int ms = 0; ms < 4; ms++)
            #pragma unroll
            for (int ns = 0; ns < 4; ns++) {
                mma16816(acc[ms][ns], ah[cur][ms], bh[cur][ns]);
                mma16816(acc[ms][ns], ah[cur][ms], bl[cur][ns]);
                mma16816(acc[ms][ns], al[cur][ms], bh[cur][ns]);
            }
    }

    const int qr = lane >> 2, qc = lane & 3;
    #pragma unroll
    for (int ns = 0; ns < 4; ns++) {
        int e = e0 + wn + ns*8 + qc*2;
        float b0 = b_in[c*768 + 256 + e];
        float b1 = b_in[c*768 + 256 + e + 1];
        float* base = (e < 256) ? g_K : g_V;
        int col = (e < 256) ? e : e - 256;
        #pragma unroll
        for (int ms = 0; ms < 4; ms++) {
            int gm0 = m0 + wm + ms*16 + qr;
            #pragma unroll
            for (int half = 0; half < 2; half++) {
                int gm = gm0 + half*8;
                if (gm >= MX) continue;
                int bb = gm / NP, pos = gm % NP;
                float2 v;
                v.x = acc[ms][ns][half*2+0] + b0;
                v.y = acc[ms][ns][half*2+1] + b1;
                *(float2*)(base + (((size_t)c*BB + bb)*NP + pos)*DD + col) = v;
            }
        }
    }
}

// ---------------- combined weight: Mc[c] = w_fuse @ w_out[c] -----------------
__global__ __launch_bounds__(256, 2)
void gemm_comb(const float* __restrict__ w_fuse, const float* __restrict__ w_out) {
    const int c  = blockIdx.z;
    const int m0 = blockIdx.x * 128;
    const int n0 = blockIdx.y * 128;
    __shared__ float As[8][128];
    __shared__ float Bs[8][128];
    const int tid  = threadIdx.x;
    const int aRow = tid >> 1, aCol = (tid & 1) << 2;
    const int bK   = tid >> 5, bN = (tid & 31) << 2;

    const float* Ap = w_fuse + (size_t)(m0 + aRow) * DD + aCol;
    const float* Bbase = w_out + (size_t)c * DD * DD;

    const int ty = tid >> 4, tx = tid & 15;
    float acc[8][8];
    #pragma unroll
    for (int i = 0; i < 8; i++)
        #pragma unroll
        for (int j = 0; j < 8; j++) acc[i][j] = 0.f;

    for (int kt = 0; kt < DD; kt += 8) {
        float4 a = *(const float4*)(Ap + kt);
        float4 b = *(const float4*)(Bbase + (size_t)(kt + bK) * DD + n0 + bN);
        As[aCol+0][aRow]=a.x; As[aCol+1][aRow]=a.y;
        As[aCol+2][aRow]=a.z; As[aCol+3][aRow]=a.w;
        *(float4*)&Bs[bK][bN] = b;
        __syncthreads();
        #pragma unroll
        for (int k = 0; k < 8; k++) {
            float ra[8], rb[8];
            *(float4*)&ra[0] = *(const float4*)&As[k][ty*8];
            *(float4*)&ra[4] = *(const float4*)&As[k][ty*8+4];
            *(float4*)&rb[0] = *(const float4*)&Bs[k][tx*8];
            *(float4*)&rb[4] = *(const float4*)&Bs[k][tx*8+4];
            #pragma unroll
            for (int i = 0; i < 8; i++)
                #pragma unroll
                for (int j = 0; j < 8; j++)
                    acc[i][j] = fmaf(ra[i], rb[j], acc[i][j]);
        }
        __syncthreads();
    }

    #pragma unroll
    for (int i = 0; i < 8; i++) {
        int m = m0 + ty*8 + i;
        float* op = g_Mc + ((size_t)c*DD + m)*DD + n0 + tx*8;
        #pragma unroll
        for (int j = 0; j < 8; j += 4) {
            float4 v; v.x=acc[i][j]; v.y=acc[i][j+1]; v.z=acc[i][j+2]; v.w=acc[i][j+3];
            *(float4*)(op + j) = v;
        }
    }
}

// ---------------- combined bias (warp per output) ------------------------------
__global__ void bias_comb(const float* __restrict__ w_fuse,
                          const float* __restrict__ b_out,
                          const float* __restrict__ b_fuse) {
    int c = blockIdx.x;
    int e = blockIdx.y * 8 + (threadIdx.x >> 5);
    int lane = threadIdx.x & 31;
    const float* wf = w_fuse + (size_t)e * DD;
    const float* bo = b_out + c * DD;
    float s = 0.f;
    #pragma unroll
    for (int i = 0; i < 8; i++) s = fmaf(wf[lane + i*32], bo[lane + i*32], s);
    #pragma unroll
    for (int o = 16; o; o >>= 1) s += __shfl_xor_sync(~0u, s, o);
    if (lane == 0) g_bc[c*DD + e] = s + b_fuse[e];
}

// ---------------- attention + fused Q projection (one CTA per (c,b)) -----------
__global__ __launch_bounds__(256)
void attn_kernel(const float* __restrict__ x, const float* __restrict__ w_in,
                 const float* __restrict__ b_in) {
    const int cb = blockIdx.x;              // 0..607
    const int c  = cb / BB;
    const int b  = cb % BB;
    __shared__ float Qs[CC*DD];             // 19 KB
    __shared__ float S[24][368];            // 34.5 KB (rows 19..23 = zero pad)
    const int tid  = threadIdx.x;
    const int wid  = tid >> 5, lane = tid & 31;

    const float* Kg = g_K  + (size_t)cb * NP * DD;
    const float* Vg = g_V  + (size_t)cb * NP * DD;
    float*       Og = g_AO + (size_t)cb * CC * DD;

    // ---- phase 0: stage x rows (19x256) into S scratch ----
    {
        float* xs = &S[0][0];
        const float* xrow = x + ((size_t)b * NP + c * CC) * DD;
        for (int i = tid; i < CC*DD; i += 256) xs[i] = xrow[i];
    }
    __syncthreads();

    // ---- phase 1: Q = xs @ wq^T + bq (warp-cooperative dots) ----
    {
        const float* xs = &S[0][0];
        const float* wq = w_in + (size_t)c * 768 * DD;
        const float* bq = b_in + c * 768;
        for (int p = wid; p < CC*DD; p += 8) {
            int e = p / CC, j = p - e*CC;
            const float* wr = wq + (size_t)e * DD;
            const float* xr = xs + j * DD;
            float s = 0.f;
            #pragma unroll
            for (int ch = 0; ch < 8; ch++)
                s = fmaf(xr[lane + ch*32], wr[lane + ch*32], s);
            #pragma unroll
            for (int o = 16; o; o >>= 1) s += __shfl_xor_sync(~0u, s, o);
            if (lane == 0) Qs[j*DD + e] = s + bq[e];
        }
    }
    __syncthreads();

    // ---- zero pad rows 19..23 of S (read by PV for j2 >= 19, contribute 0) ----
    for (int i = tid; i < 5*368; i += 256) (&S[19][0])[i] = 0.f;
    __syncthreads();

    const float scale = 0.17677669529663687f;   // 1/sqrt(32)

    for (int h = 0; h < HH; h++) {
        const int hoff = h * HDIM;
        // ---- scores + mask (float4 Q, 4 partial sums) ----
        for (int k = tid; k < NP; k += 256) {
            float4 kr[8];
            const float4* kp = (const float4*)(Kg + (size_t)k * DD + hoff);
            #pragma unroll
            for (int q = 0; q < 8; q++) kr[q] = kp[q];
            int ki = k / CC, kj = k - ki*CC;
            for (int j = 0; j < CC; j++) {
                const float4* qp = (const float4*)&Qs[j*DD + hoff];
                float s0 = 0.f, s1 = 0.f, s2 = 0.f, s3 = 0.f;
                #pragma unroll
                for (int q = 0; q < 8; q++) {
                    float4 qv = qp[q];
                    s0 = fmaf(kr[q].x, qv.x, s0);
                    s1 = fmaf(kr[q].y, qv.y, s1);
                    s2 = fmaf(kr[q].z, qv.z, s2);
                    s3 = fmaf(kr[q].w, qv.w, s3);
                }
                float s = (s0 + s1) + (s2 + s3);
                bool ok = (ki == c) | (kj == c) | (ki == j) | (kj == j);
                S[j][k] = ok ? s * scale : -1e30f;
            }
        }
        __syncthreads();
        // ---- softmax, one warp per row ----
        {
            for (int j = wid; j < CC; j += 8) {
                float mx = -1e30f;
                for (int k = lane; k < NP; k += 32) mx = fmaxf(mx, S[j][k]);
                #pragma unroll
                for (int o = 16; o; o >>= 1) mx = fmaxf(mx, __shfl_xor_sync(~0u, mx, o));
                float sum = 0.f;
                for (int k = lane; k < NP; k += 32) {
                    float e = __expf(S[j][k] - mx);
                    S[j][k] = e; sum += e;
                }
                #pragma unroll
                for (int o = 16; o; o >>= 1) sum += __shfl_xor_sync(~0u, sum, o);
                float inv = 1.f / sum;
                for (int k = lane; k < NP; k += 32) S[j][k] *= inv;
            }
        }
        __syncthreads();
        // ---- P @ V : unrolled x4, no branches in loop ----
        {
            const int d = lane, jg = wid;
            const float* vp = Vg + hoff + d;
            float o0 = 0.f, o1 = 0.f, o2 = 0.f;
            for (int k = 0; k < 360; k += 4) {
                float v0 = vp[(size_t)(k+0) * DD];
                float v1 = vp[(size_t)(k+1) * DD];
                float v2 = vp[(size_t)(k+2) * DD];
                float v3 = vp[(size_t)(k+3) * DD];
                float4 sA = *(const float4*)&S[jg   ][k];
                float4 sB = *(const float4*)&S[jg+8 ][k];
                float4 sC = *(const float4*)&S[jg+16][k];
                o0 = fmaf(sA.x, v0, o0); o1 = fmaf(sB.x, v0, o1); o2 = fmaf(sC.x, v0, o2);
                o0 = fmaf(sA.y, v1, o0); o1 = fmaf(sB.y, v1, o1); o2 = fmaf(sC.y, v1, o2);
                o0 = fmaf(sA.z, v2, o0); o1 = fmaf(sB.z, v2, o1); o2 = fmaf(sC.z, v2, o2);
                o0 = fmaf(sA.w, v3, o0); o1 = fmaf(sB.w, v3, o1); o2 = fmaf(sC.w, v3, o2);
            }
            {   // tail k = 360
                float v = vp[(size_t)360 * DD];
                o0 = fmaf(S[jg   ][360], v, o0);
                o1 = fmaf(S[jg+8 ][360], v, o1);
                o2 = fmaf(S[jg+16][360], v, o2);
            }
            Og[jg*DD + hoff + d]     = o0;
            Og[(jg+8)*DD + hoff + d] = o1;
            if (jg + 16 < CC) Og[(jg+16)*DD + hoff + d] = o2;
        }
        __syncthreads();
    }
}

// ---------------- out-proj + fuse + residual ----------------------------------
__global__ __launch_bounds__(256, 2)
void out_fuse(const float* __restrict__ x, float* __restrict__ y) {
    const int c  = blockIdx.z;
    const int m0 = blockIdx.x * 128;
    const int n0 = blockIdx.y * 128;
    __shared__ float As[8][128];
    __shared__ float Bs[8][128];
    const int tid   = threadIdx.x;
    const int ldRow = tid >> 1;
    const int ldCol = (tid & 1) << 2;

    int am = m0 + ldRow; if (am > MQ - 1) am = MQ - 1;
    const float* Ap = g_AO + ((size_t)c*MQ + am) * DD + ldCol;
    const float* Bp = g_Mc + ((size_t)c*DD + n0 + ldRow) * DD + ldCol;

    const int ty = tid >> 4, tx = tid & 15;
    float acc[8][8];
    #pragma unroll
    for (int i = 0; i < 8; i++)
        #pragma unroll
        for (int j = 0; j < 8; j++) acc[i][j] = 0.f;

    for (int kt = 0; kt < DD; kt += 8) {
        float4 a = *(const float4*)(Ap + kt);
        float4 b = *(const float4*)(Bp + kt);
        As[ldCol+0][ldRow]=a.x; As[ldCol+1][ldRow]=a.y;
        As[ldCol+2][ldRow]=a.z; As[ldCol+3][ldRow]=a.w;
        Bs[ldCol+0][ldRow]=b.x; Bs[ldCol+1][ldRow]=b.y;
        Bs[ldCol+2][ldRow]=b.z; Bs[ldCol+3][ldRow]=b.w;
        __syncthreads();
        #pragma unroll
        for (int k = 0; k < 8; k++) {
            float ra[8], rb[8];
            *(float4*)&ra[0] = *(const float4*)&As[k][ty*8];
            *(float4*)&ra[4] = *(const float4*)&As[k][ty*8+4];
            *(float4*)&rb[0] = *(const float4*)&Bs[k][tx*8];
            *(float4*)&rb[4] = *(const float4*)&Bs[k][tx*8+4];
            #pragma unroll
            for (int i = 0; i < 8; i++)
                #pragma unroll
                for (int j = 0; j < 8; j++)
                    acc[i][j] = fmaf(ra[i], rb[j], acc[i][j]);
        }
        __syncthreads();
    }

    const float* bcp = g_bc + c*DD + n0 + tx*8;
    float bv[8];
    #pragma unroll
    for (int j = 0; j < 8; j++) bv[j] = bcp[j];

    #pragma unroll
    for (int i = 0; i < 8; i++) {
        int m = m0 + ty*8 + i;
        if (m >= MQ) break;
        int bb = m / CC, j = m % CC;
        size_t row = (size_t)bb * NP + c * CC + j;
        float*       op = y + row*DD + n0 + tx*8;
        const float* xp = x + row*DD + n0 + tx*8;
        #pragma unroll
        for (int jj = 0; jj < 8; jj += 4) {
            float4 xv = *(const float4*)(xp + jj);
            float4 v;
            v.x = acc[i][jj+0] + bv[jj+0] + xv.x;
            v.y = acc[i][jj+1] + bv[jj+1] + xv.y;
            v.z = acc[i][jj+2] + bv[jj+2] + xv.z;
            v.w = acc[i][jj+3] + bv[jj+3] + xv.w;
            *(float4*)(op + jj) = v;
        }
    }
}

// ---------------- launch -------------------------------------------------------
extern "C" void kernel_launch(void* const* d_in, const int* in_sizes, int n_in,
                              void* d_out, int out_size) {
    const float* x      = (const float*)d_in[0];
    const float* w_in   = (const float*)d_in[1];
    const float* b_in   = (const float*)d_in[2];
    const float* w_out  = (const float*)d_in[3];
    const float* b_out  = (const float*)d_in[4];
    const float* w_fuse = (const float*)d_in[5];
    const float* b_fuse = (const float*)d_in[6];
    float* y = (float*)d_out;

    __nv_bfloat16 *xh, *xl, *wh, *wl;
    cudaGetSymbolAddress((void**)&xh, g_xh);
    cudaGetSymbolAddress((void**)&xl, g_xl);
    cudaGetSymbolAddress((void**)&wh, g_wh);
    cudaGetSymbolAddress((void**)&wl, g_wl);

    cudaFuncSetAttribute(gemm_kv_mma, cudaFuncAttributeMaxDynamicSharedMemorySize, KV_SMEM);

    // launch order: attn is launch #4 -> profiled by ncu capture window
    {
        int n4 = (MX*DD)/4;
        split_bf16<<<(n4 + 255)/256, 256>>>(x, xh, xl, n4);                 // 1
    }
    {
        int n4 = (CC*768*DD)/4;
        split_bf16<<<(n4 + 255)/256, 256>>>(w_in, wh, wl, n4);              // 2
    }

    dim3 gkv((MX + 127) / 128, NTOT / 128);   // (91, 76)
    gemm_kv_mma<<<gkv, 256, KV_SMEM>>>(b_in);                               // 3

    attn_kernel<<<CC*BB, 256>>>(x, w_in, b_in);                             // 4 (profiled)

    dim3 gc(2, 2, CC);
    gemm_comb<<<gc, 256>>>(w_fuse, w_out);                                  // 5
    bias_comb<<<dim3(CC, DD/8), 256>>>(w_fuse, b_out, b_fuse);              // 6

    dim3 gq((MQ + 127) / 128, 2, CC);
    out_fuse<<<gq, 256>>>(x, y);                                            // 7
}